// round 5
// baseline (speedup 1.0000x reference)
#include <cuda_runtime.h>
#include <cuda_fp16.h>
#include <cstdint>

// Problem constants
#define BB   32
#define TT   64
#define SS   64
#define HH   256
#define VV   32000
#define NBLK 128   // persistent recurrence grid

// ---------------------------------------------------------------------------
// PTX helpers (plain sm_103 feature set: cp.async, ldmatrix, mma.sync)
// ---------------------------------------------------------------------------
__device__ __forceinline__ uint32_t smem_u32(const void* p) {
    uint32_t a;
    asm("{ .reg .u64 t; cvta.to.shared.u64 t, %1; cvt.u32.u64 %0, t; }" : "=r"(a) : "l"(p));
    return a;
}
__device__ __forceinline__ void cp_async16(uint32_t dst, const void* src) {
    asm volatile("cp.async.cg.shared.global [%0], [%1], 16;" :: "r"(dst), "l"(src));
}
#define CP_COMMIT() asm volatile("cp.async.commit_group;" ::: "memory")
#define CP_WAIT(n)  asm volatile("cp.async.wait_group %0;" :: "n"(n) : "memory")

__device__ __forceinline__ void ldsm_x4(uint32_t addr, uint32_t& r0, uint32_t& r1,
                                        uint32_t& r2, uint32_t& r3) {
    asm volatile("ldmatrix.sync.aligned.m8n8.x4.shared.b16 {%0,%1,%2,%3}, [%4];"
                 : "=r"(r0), "=r"(r1), "=r"(r2), "=r"(r3) : "r"(addr));
}
__device__ __forceinline__ void mma16816(float* c, const uint32_t* a,
                                         uint32_t b0, uint32_t b1) {
    asm volatile("mma.sync.aligned.m16n8k16.row.col.f32.f16.f16.f32 "
                 "{%0,%1,%2,%3}, {%4,%5,%6,%7}, {%8,%9}, {%0,%1,%2,%3};"
                 : "+f"(c[0]), "+f"(c[1]), "+f"(c[2]), "+f"(c[3])
                 : "r"(a[0]), "r"(a[1]), "r"(a[2]), "r"(a[3]), "r"(b0), "r"(b1));
}

// ---------------------------------------------------------------------------
// Device scratch
// ---------------------------------------------------------------------------
__device__ __align__(16) float g_Wcat[256 * 1024];
__device__ __align__(16) float g_bcat[1024];
__device__ __align__(16) float g_Wann[256 * 1024];
__device__ __align__(16) float g_Wx[256 * 768];
__device__ __align__(16) float g_annprojT[256 * 2048];
__device__ __align__(16) float g_annWi[2048 * 768];
__device__ __align__(16) float g_xproj[2048 * 768];
__device__ __align__(16) float g_hcat[32 * 1024];
__device__ __align__(16) float g_upart[32 * 2048];
__device__ __align__(16) float g_hbuf[32 * 256];
__device__ __align__(16) __half g_Ah[2048 * 512];    // [A_hi(256) | A_lo(256)] per row
__device__ __align__(16) __half g_Bh[32000L * 256];  // B_hi only, K-major

// tree barrier state: 8 leaf counters (16 CTAs each) + root
__device__ unsigned g_cnt[9];
__device__ volatile unsigned g_gen;

// ---------------------------------------------------------------------------
// Two-level grid barrier: arrival contention 16/address instead of 128
// ---------------------------------------------------------------------------
__device__ __forceinline__ void grid_barrier(int c) {
    __syncthreads();
    if (threadIdx.x == 0) {
        unsigned gen = g_gen;
        __threadfence();
        if (atomicAdd(&g_cnt[c >> 4], 1u) == 15u) {
            if (atomicAdd(&g_cnt[8], 1u) == 7u) {
                // last CTA of last leaf: reset all counters, flip generation
#pragma unroll
                for (int i = 0; i < 9; i++) g_cnt[i] = 0u;
                __threadfence();
                g_gen = gen + 1;
            }
        }
        while (g_gen == gen) { }
        __threadfence();
    }
    __syncthreads();
}

// ---------------------------------------------------------------------------
// K0: build fused weight matrices
// ---------------------------------------------------------------------------
__global__ void prep_kernel(const float* __restrict__ W1,
                            const float* __restrict__ Wiz, const float* __restrict__ Wir,
                            const float* __restrict__ Wih,
                            const float* __restrict__ Whz, const float* __restrict__ bhz,
                            const float* __restrict__ Whr, const float* __restrict__ bhr,
                            const float* __restrict__ Whh, const float* __restrict__ bhh) {
    int idx = blockIdx.x * blockDim.x + threadIdx.x;
    int stride = gridDim.x * blockDim.x;
    for (int i = idx; i < 256 * 1024; i += stride) {
        int k = i >> 10, j = i & 1023;
        float wc, wa;
        if (j < 256)      { wc = W1[k * 256 + j];          wa = W1[(256 + k) * 256 + j]; }
        else if (j < 512) { wc = Whz[k * 256 + j - 256];   wa = Wiz[k * 256 + j - 256]; }
        else if (j < 768) { wc = Whr[k * 256 + j - 512];   wa = Wir[k * 256 + j - 512]; }
        else              { wc = Whh[k * 256 + j - 768];   wa = Wih[k * 256 + j - 768]; }
        g_Wcat[i] = wc; g_Wann[i] = wa;
    }
    for (int i = idx; i < 256 * 768; i += stride) {
        int k = i / 768, j = i % 768;
        float w;
        if (j < 256)      w = Wiz[(256 + k) * 256 + j];
        else if (j < 512) w = Wir[(256 + k) * 256 + j - 256];
        else              w = Wih[(256 + k) * 256 + j - 512];
        g_Wx[i] = w;
    }
    for (int i = idx; i < 1024; i += stride) {
        float bv = 0.f;
        if (i >= 256 && i < 512)      bv = bhz[i - 256];
        else if (i >= 512 && i < 768) bv = bhr[i - 512];
        else if (i >= 768)            bv = bhh[i - 768];
        g_bcat[i] = bv;
    }
}

// ---------------------------------------------------------------------------
// K1 combo: sgemm mode1 (512 CTAs) + sgemm mode2 (384) + Wout->fp16 (4000)
// ---------------------------------------------------------------------------
__global__ void __launch_bounds__(128)
combo_kernel(const float* __restrict__ ann, const float* __restrict__ emb,
             const int* __restrict__ inputs, const float* __restrict__ Wout,
             const float* __restrict__ b1, const float* __restrict__ biz,
             const float* __restrict__ bir, const float* __restrict__ bih) {
    __shared__ __align__(16) float sm[2][64 * 20 + 16 * 68];
    __shared__ __align__(16) float sw[32 * 68];
    __shared__ int tok[64];

    const int bid = blockIdx.x, tid = threadIdx.x;

    if (bid >= 896) {
        int b3 = bid - 896;
        int k0 = (b3 & 7) * 32, n0 = (b3 >> 3) * 64;
        for (int i = tid; i < 32 * 64; i += 128) {
            int k = i >> 6, n = i & 63;
            sw[k * 68 + n] = Wout[(size_t)(k0 + k) * VV + n0 + n];
        }
        __syncthreads();
        const int n = tid >> 1, kh = (tid & 1) * 16;
        __align__(16) __half vals[16];
#pragma unroll
        for (int j = 0; j < 16; j++) vals[j] = __float2half(sw[(kh + j) * 68 + n]);
        __half* dst = g_Bh + (size_t)(n0 + n) * 256 + k0 + kh;
        *(uint4*)dst       = ((const uint4*)vals)[0];
        *(uint4*)(dst + 8) = ((const uint4*)vals)[1];
        return;
    }

    const bool m1 = bid < 512;
    int row0, col0, N;
    const float* Bm;
    if (m1) { row0 = (bid >> 4) * 64; col0 = (bid & 15) * 64; N = 1024; Bm = g_Wann; }
    else    { int b2 = bid - 512; row0 = (b2 / 12) * 64; col0 = (b2 % 12) * 64; N = 768; Bm = g_Wx; }

    if (!m1 && tid < 64) {
        int r = row0 + tid;
        tok[tid] = inputs[(r & 31) * TT + (r >> 5)];
    }
    if (!m1) __syncthreads();

    const int rA = tid >> 2, kqA = (tid & 3) * 4;
    const int kB = tid >> 4, nB = (tid & 15) * 4;
    const float* ArowA = m1 ? (ann + (size_t)(row0 + rA) * 256)
                            : (emb + (size_t)tok[rA] * 256);
    const float* ArowB = m1 ? (ann + (size_t)(row0 + rA + 32) * 256)
                            : (emb + (size_t)tok[rA + 32] * 256);
    const float* Bcol = Bm + col0;

    {
        float4 a0 = *(const float4*)(ArowA + kqA);
        float4 a1 = *(const float4*)(ArowB + kqA);
        float4 b0 = *(const float4*)(Bcol + (size_t)kB * N + nB);
        float4 b1v = *(const float4*)(Bcol + (size_t)(kB + 8) * N + nB);
        *(float4*)&sm[0][rA * 20 + kqA]        = a0;
        *(float4*)&sm[0][(rA + 32) * 20 + kqA] = a1;
        *(float4*)&sm[0][1280 + kB * 68 + nB]        = b0;
        *(float4*)&sm[0][1280 + (kB + 8) * 68 + nB]  = b1v;
    }
    __syncthreads();

    float acc[4][8];
#pragma unroll
    for (int i = 0; i < 4; i++)
#pragma unroll
        for (int j = 0; j < 8; j++) acc[i][j] = 0.f;

    const int ty4 = (tid >> 3) * 4, tx8 = (tid & 7) * 8;
    int buf = 0;

#pragma unroll 1
    for (int kt = 0; kt < 16; kt++) {
        float4 nA0, nA1, nB0, nB1;
        if (kt < 15) {
            int k0 = (kt + 1) * 16;
            nA0 = *(const float4*)(ArowA + k0 + kqA);
            nA1 = *(const float4*)(ArowB + k0 + kqA);
            nB0 = *(const float4*)(Bcol + (size_t)(k0 + kB) * N + nB);
            nB1 = *(const float4*)(Bcol + (size_t)(k0 + kB + 8) * N + nB);
        }
        const float* As_ = &sm[buf][0];
        const float* Bs_ = &sm[buf][1280];
#pragma unroll
        for (int kk = 0; kk < 16; kk++) {
            float a[4], b[8];
#pragma unroll
            for (int i = 0; i < 4; i++) a[i] = As_[(ty4 + i) * 20 + kk];
            *(float4*)&b[0] = *(const float4*)&Bs_[kk * 68 + tx8];
            *(float4*)&b[4] = *(const float4*)&Bs_[kk * 68 + tx8 + 4];
#pragma unroll
            for (int i = 0; i < 4; i++)
#pragma unroll
                for (int j = 0; j < 8; j++) acc[i][j] += a[i] * b[j];
        }
        if (kt < 15) {
            buf ^= 1;
            __syncthreads();
            *(float4*)&sm[buf][rA * 20 + kqA]        = nA0;
            *(float4*)&sm[buf][(rA + 32) * 20 + kqA] = nA1;
            *(float4*)&sm[buf][1280 + kB * 68 + nB]        = nB0;
            *(float4*)&sm[buf][1280 + (kB + 8) * 68 + nB]  = nB1;
            __syncthreads();
        }
    }

#pragma unroll
    for (int i = 0; i < 4; i++) {
        int r = row0 + ty4 + i;
#pragma unroll
        for (int j = 0; j < 8; j++) {
            int cidx = col0 + tx8 + j;
            float v = acc[i][j];
            if (m1) {
                if (cidx < 256) g_annprojT[cidx * 2048 + r] = v + b1[cidx];
                else            g_annWi[(size_t)r * 768 + (cidx - 256)] = v;
            } else {
                float bv = (cidx < 256) ? biz[cidx]
                         : (cidx < 512) ? bir[cidx - 256] : bih[cidx - 512];
                g_xproj[(size_t)r * 768 + cidx] = v + bv;
            }
        }
    }
}

// ---------------------------------------------------------------------------
// K3: persistent recurrence (tree barrier; smem-cached attention slice)
// ---------------------------------------------------------------------------
#define REC_DSMEM ((32 * 260 + 8 * 260 + 8 * 2048) * 4)

__global__ void __launch_bounds__(256, 1)
recurrence_kernel(const float* __restrict__ hidden_init,
                  const float* __restrict__ W2,
                  float* __restrict__ att_out) {
    extern __shared__ __align__(16) float dsm[];
    float* hs   = dsm;               // 32 x 260
    float* wsT  = dsm + 32 * 260;    // 8 x 260
    float* annp = wsT + 8 * 260;     // 8 x 2048 (CTAs < 32 only)

    __shared__ float bsA[8];
    __shared__ float W2s[256];
    __shared__ float qs[32 * 8];
    __shared__ float usq[4][64];
    __shared__ float us[64];
    __shared__ float gz[64], gr[64], gh[64];

    const int c = blockIdx.x, tid = threadIdx.x;

    for (int i = tid; i < 2048; i += 256) {
        int j = i >> 8, k = i & 255;
        wsT[j * 260 + k] = g_Wcat[k * 1024 + c * 8 + j];
    }
    if (tid < 8) bsA[tid] = g_bcat[c * 8 + tid];
    W2s[tid] = W2[tid];
    { int i = c * 256 + tid; if (i < 32 * 256) g_hbuf[i] = hidden_init[i]; }
    if (c < 32) {
        const float* src = g_annprojT + c * 8 * 2048;
        for (int i = tid * 4; i < 8 * 2048; i += 1024)
            *(float4*)&annp[i] = *(const float4*)&src[i];
    }
    grid_barrier(c);

    const int myb = c >> 2, myds = c & 3;
    const int bA = tid >> 3, jA = tid & 7;

    for (int t = 0; t < TT; t++) {
        // ---- Phase A: hcat = h @ Wcat ----
        for (int i = tid * 4; i < 32 * 256; i += 1024) {
            float4 v = *(const float4*)(g_hbuf + i);
            *(float4*)&hs[(i >> 8) * 260 + (i & 255)] = v;
        }
        __syncthreads();
        {
            float a = bsA[jA];
            const float* hp = &hs[bA * 260];
            const float* wp = &wsT[jA * 260];
#pragma unroll
            for (int k = 0; k < 256; k += 4) {
                float4 hv = *(const float4*)(hp + k);
                float4 wv = *(const float4*)(wp + k);
                a += hv.x * wv.x + hv.y * wv.y + hv.z * wv.z + hv.w * wv.w;
            }
            g_hcat[bA * 1024 + c * 8 + jA] = a;
            if (c < 32) qs[bA * 8 + jA] = a;
        }
        if (c < 32) {
            __syncthreads();
#pragma unroll
            for (int rep = 0; rep < 8; rep++) {
                int bs = rep * 256 + tid;
                int b = bs >> 6;
                float a = 0.f;
#pragma unroll
                for (int j = 0; j < 8; j++) {
                    float v = qs[b * 8 + j] + annp[j * 2048 + bs];
                    a += W2s[c * 8 + j] * fmaxf(v, 0.f);
                }
                g_upart[c * 2048 + bs] = a;
            }
        }
        grid_barrier(c);

        // ---- Phase B ----
        {
            int s = tid & 63, q = tid >> 6;
            float u = 0.f;
#pragma unroll
            for (int cc = q * 8; cc < q * 8 + 8; cc++)
                u += g_upart[cc * 2048 + myb * 64 + s];
            usq[q][s] = u;
        }
        __syncthreads();
        if (tid < 32) {
            float v0 = usq[0][tid] + usq[1][tid] + usq[2][tid] + usq[3][tid];
            int t2 = tid + 32;
            float v1 = usq[0][t2] + usq[1][t2] + usq[2][t2] + usq[3][t2];
            float m = fmaxf(v0, v1);
#pragma unroll
            for (int o = 16; o; o >>= 1) m = fmaxf(m, __shfl_xor_sync(0xffffffffu, m, o));
            float e0 = __expf(v0 - m), e1 = __expf(v1 - m);
            float ssum = e0 + e1;
#pragma unroll
            for (int o = 16; o; o >>= 1) ssum += __shfl_xor_sync(0xffffffffu, ssum, o);
            float inv = 1.f / ssum;
            us[tid] = e0 * inv; us[t2] = e1 * inv;
        }
        __syncthreads();
        if (myds == 0 && tid < 64)
            att_out[(myb * SS + tid) * TT + t] = us[tid];
        if (tid < 192) {
            int g = tid >> 6, dd = tid & 63;
            const float* colp = g_annWi + (size_t)(myb * 64) * 768 + g * 256 + myds * 64 + dd;
            float acc = 0.f;
#pragma unroll 16
            for (int s = 0; s < 64; s++) acc += us[s] * colp[(size_t)s * 768];
            (g == 0 ? gz : g == 1 ? gr : gh)[dd] = acc;
        }
        __syncthreads();
        if (tid < 64) {
            int d = myds * 64 + tid;
            const float* xp = g_xproj + (size_t)(t * 32 + myb) * 768;
            const float* hc = g_hcat + myb * 1024;
            float z  = 1.f / (1.f + __expf(-(gz[tid] + xp[d]       + hc[256 + d])));
            float r  = 1.f / (1.f + __expf(-(gr[tid] + xp[256 + d] + hc[512 + d])));
            float g2 = tanhf(gh[tid] + xp[512 + d] + r * hc[768 + d]);
            float hold = g_hbuf[myb * 256 + d];
            float hn = (1.f - z) * g2 + z * hold;
            g_hbuf[myb * 256 + d] = hn;
            __half hi = __float2half(hn);
            __half lo = __float2half(hn - __half2float(hi));
            size_t rb = (size_t)(myb * 64 + t) * 512;
            g_Ah[rb + d]       = hi;
            g_Ah[rb + 256 + d] = lo;
        }
        grid_barrier(c);
    }
}

// ---------------------------------------------------------------------------
// K4: HMMA fp16 GEMM, A-strip resident in SMEM.
// D[2048,32000] = Ah[2048,512] @ Bh[32000,256]^T  (A_hi and A_lo share B)
// grid (16,125): CTA caches 128x512 A (128 KB), 2 col-subtiles of 128,
// B streamed in 8 KB double-buffered chunks; each B chunk feeds 2 k-steps.
// ---------------------------------------------------------------------------
#define GEMM_DSMEM (131072 + 16384)

__global__ void __launch_bounds__(256, 1)
gemm_mma_kernel(const float* __restrict__ bout, float* __restrict__ out) {
    extern __shared__ char gsm[];
    const uint32_t sAb = smem_u32(gsm);
    const uint32_t sBb = sAb + 131072;

    const int tid = threadIdx.x;
    const int lane = tid & 31, wid = tid >> 5;
    const int wr = wid >> 2, wc = wid & 3;
    const int row0 = blockIdx.x * 128;
    const int colbase = blockIdx.y * 256;

    // ---- load full A strip (128 x 512 fp16 = 128 KB), 16 swizzled blocks ----
    {
        const __half* Ag = g_Ah + (size_t)row0 * 512;
#pragma unroll
        for (int i = 0; i < 32; i++) {
            int cch = tid + i * 256;             // 0..8191
            int kt = cch >> 9;
            int r  = (cch >> 2) & 127;
            int c4 = cch & 3;
            uint32_t dst = sAb + kt * 8192 + r * 64 + ((c4 ^ ((r >> 1) & 3)) * 16);
            cp_async16(dst, Ag + (size_t)r * 512 + kt * 32 + c4 * 8);
        }
    }
    CP_COMMIT();

    const int aRow = lane & 15, aSel = lane >> 4;
    const int bRow = (lane & 7) + ((lane >> 4) << 3), bSel = (lane >> 3) & 1;

    const int rB0 = tid >> 2, cB = tid & 3;
    const int rB1 = rB0 + 64;
    const uint32_t dB0 = rB0 * 64 + ((cB ^ ((rB0 >> 1) & 3)) * 16);
    const uint32_t dB1 = rB1 * 64 + ((cB ^ ((rB1 >> 1) & 3)) * 16);

    CP_WAIT(0);
    __syncthreads();   // A resident

    const __half* Bg;
#define LOAD_B(bk) do {                                                        \
        uint32_t bb_ = sBb + ((bk) & 1) * 8192;                                \
        cp_async16(bb_ + dB0, Bg + (size_t)rB0 * 256 + (bk) * 32 + cB * 8);    \
        cp_async16(bb_ + dB1, Bg + (size_t)rB1 * 256 + (bk) * 32 + cB * 8);    \
    } while (0)

#pragma unroll 1
    for (int ns = 0; ns < 2; ns++) {
        const int col0 = colbase + ns * 128;
        Bg = g_Bh + (size_t)col0 * 256;

        LOAD_B(0); CP_COMMIT();
        LOAD_B(1); CP_COMMIT();

        float acc[4][4][4];
#pragma unroll
        for (int i = 0; i < 4; i++)
#pragma unroll
            for (int j = 0; j < 4; j++)
#pragma unroll
                for (int q = 0; q < 4; q++) acc[i][j][q] = 0.f;

#pragma unroll 1
        for (int bk = 0; bk < 8; bk++) {
            CP_WAIT(1);
            __syncthreads();
            const uint32_t bb = sBb + (bk & 1) * 8192;
#pragma unroll
            for (int kf = 0; kf < 2; kf++) {
                uint32_t bF[2][4];
#pragma unroll
                for (int nf2 = 0; nf2 < 2; nf2++) {
                    int row = wc * 32 + nf2 * 16 + bRow;
                    int ch  = (kf * 2 + bSel) ^ ((row >> 1) & 3);
                    ldsm_x4(bb + row * 64 + ch * 16,
                            bF[nf2][0], bF[nf2][1], bF[nf2][2], bF[nf2][3]);
                }
#pragma unroll
                for (int half = 0; half < 2; half++) {
                    const uint32_t ab = sAb + (bk + half * 8) * 8192;
                    uint32_t aF[4][4];
#pragma unroll
                    for (int mf = 0; mf < 4; mf++) {
                        int row = wr * 64 + mf * 16 + aRow;
                        int ch  = (kf * 2 + aSel) ^ ((row >> 1) & 3);
                        ldsm_x4(ab + row * 64 + ch * 16,
                                aF[mf][0], aF[mf][1], aF[mf][2], aF[mf][3]);
                    }
#pragma unroll
                    for (int mf = 0; mf < 4; mf++)
#pragma unroll
                        for (int nf = 0; nf < 4; nf++)
                            mma16816(acc[mf][nf], aF[mf],
                                     bF[nf >> 1][(nf & 1) * 2],
                                     bF[nf >> 1][(nf & 1) * 2 + 1]);
                }
            }
            __syncthreads();
            if (bk < 6) LOAD_B(bk + 2);
            CP_COMMIT();
        }

        // epilogue: direct float2 stores + bias
        const int rq = lane >> 2, cq = (lane & 3) * 2;
        const int rbase = row0 + wr * 64, cbase = col0 + wc * 32;
#pragma unroll
        for (int mf = 0; mf < 4; mf++)
#pragma unroll
            for (int nf = 0; nf < 4; nf++) {
                int r  = rbase + mf * 16 + rq;
                int cc = cbase + nf * 8 + cq;
                float bz0 = bout[cc], bz1 = bout[cc + 1];
                *(float2*)&out[(size_t)r * VV + cc] =
                    make_float2(acc[mf][nf][0] + bz0, acc[mf][nf][1] + bz1);
                *(float2*)&out[(size_t)(r + 8) * VV + cc] =
                    make_float2(acc[mf][nf][2] + bz0, acc[mf][nf][3] + bz1);
            }
    }
#undef LOAD_B
}

// ---------------------------------------------------------------------------
extern "C" void kernel_launch(void* const* d_in, const int* in_sizes, int n_in,
                              void* d_out, int out_size) {
    const int*   inputs = (const int*)  d_in[0];
    const float* ann    = (const float*)d_in[1];
    const float* hinit  = (const float*)d_in[2];
    const float* emb    = (const float*)d_in[3];
    const float* W1     = (const float*)d_in[4];
    const float* b1     = (const float*)d_in[5];
    const float* W2     = (const float*)d_in[6];
    /* b2 (d_in[7]) cancels in softmax */
    const float* Wiz    = (const float*)d_in[8];
    const float* biz    = (const float*)d_in[9];
    const float* Wir    = (const float*)d_in[10];
    const float* bir    = (const float*)d_in[11];
    const float* Wih    = (const float*)d_in[12];
    const float* bih    = (const float*)d_in[13];
    const float* Whz    = (const float*)d_in[14];
    const float* bhz    = (const float*)d_in[15];
    const float* Whr    = (const float*)d_in[16];
    const float* bhr    = (const float*)d_in[17];
    const float* Whh    = (const float*)d_in[18];
    const float* bhh    = (const float*)d_in[19];
    const float* Wout   = (const float*)d_in[20];
    const float* bout   = (const float*)d_in[21];

    float* out = (float*)d_out;
    float* att = out + (size_t)BB * TT * VV;

    static int attr_set = 0;
    if (!attr_set) {
        cudaFuncSetAttribute(recurrence_kernel,
                             cudaFuncAttributeMaxDynamicSharedMemorySize, REC_DSMEM);
        cudaFuncSetAttribute(gemm_mma_kernel,
                             cudaFuncAttributeMaxDynamicSharedMemorySize, GEMM_DSMEM);
        attr_set = 1;
    }

    prep_kernel<<<256, 256>>>(W1, Wiz, Wir, Wih, Whz, bhz, Whr, bhr, Whh, bhh);
    combo_kernel<<<4896, 128>>>(ann, emb, inputs, Wout, b1, biz, bir, bih);
    recurrence_kernel<<<NBLK, 256, REC_DSMEM>>>(hinit, W2, att);
    gemm_mma_kernel<<<dim3(16, 125), 256, GEMM_DSMEM>>>(bout, out);
}

// round 6
// speedup vs baseline: 1.0172x; 1.0172x over previous
#include <cuda_runtime.h>
#include <cuda_fp16.h>
#include <cstdint>

// Problem constants
#define BB   32
#define TT   64
#define SS   64
#define HH   256
#define VV   32000

// ---------------------------------------------------------------------------
// PTX helpers (plain sm_103 feature set: cp.async, ldmatrix, mma.sync, clusters)
// ---------------------------------------------------------------------------
__device__ __forceinline__ uint32_t smem_u32(const void* p) {
    uint32_t a;
    asm("{ .reg .u64 t; cvta.to.shared.u64 t, %1; cvt.u32.u64 %0, t; }" : "=r"(a) : "l"(p));
    return a;
}
__device__ __forceinline__ void cp_async16(uint32_t dst, const void* src) {
    asm volatile("cp.async.cg.shared.global [%0], [%1], 16;" :: "r"(dst), "l"(src));
}
#define CP_COMMIT() asm volatile("cp.async.commit_group;" ::: "memory")
#define CP_WAIT(n)  asm volatile("cp.async.wait_group %0;" :: "n"(n) : "memory")

__device__ __forceinline__ void ldsm_x4(uint32_t addr, uint32_t& r0, uint32_t& r1,
                                        uint32_t& r2, uint32_t& r3) {
    asm volatile("ldmatrix.sync.aligned.m8n8.x4.shared.b16 {%0,%1,%2,%3}, [%4];"
                 : "=r"(r0), "=r"(r1), "=r"(r2), "=r"(r3) : "r"(addr));
}
__device__ __forceinline__ void mma16816(float* c, const uint32_t* a,
                                         uint32_t b0, uint32_t b1) {
    asm volatile("mma.sync.aligned.m16n8k16.row.col.f32.f16.f16.f32 "
                 "{%0,%1,%2,%3}, {%4,%5,%6,%7}, {%8,%9}, {%0,%1,%2,%3};"
                 : "+f"(c[0]), "+f"(c[1]), "+f"(c[2]), "+f"(c[3])
                 : "r"(a[0]), "r"(a[1]), "r"(a[2]), "r"(a[3]), "r"(b0), "r"(b1));
}

// cluster helpers (sm_90 baseline features — not "a"-gated)
__device__ __forceinline__ uint32_t ctarank() {
    uint32_t r; asm("mov.u32 %0, %%cluster_ctarank;" : "=r"(r)); return r;
}
__device__ __forceinline__ uint32_t mapa_u32(uint32_t laddr, uint32_t rank) {
    uint32_t r;
    asm("mapa.shared::cluster.u32 %0, %1, %2;" : "=r"(r) : "r"(laddr), "r"(rank));
    return r;
}
__device__ __forceinline__ void st_cluster_f32(uint32_t addr, float v) {
    asm volatile("st.shared::cluster.f32 [%0], %1;" :: "r"(addr), "f"(v) : "memory");
}
__device__ __forceinline__ float ld_cluster_f32(uint32_t addr) {
    float v;
    asm volatile("ld.shared::cluster.f32 %0, [%1];" : "=f"(v) : "r"(addr) : "memory");
    return v;
}
#define CLUSTER_SYNC() do { \
    asm volatile("barrier.cluster.arrive.aligned;" ::: "memory"); \
    asm volatile("barrier.cluster.wait.aligned;" ::: "memory"); \
} while (0)

// ---------------------------------------------------------------------------
// Device scratch
// ---------------------------------------------------------------------------
__device__ __align__(16) float g_Wcat[256 * 1024];     // [k][qproj|Whz|Whr|Whh]
__device__ __align__(16) float g_bcat[1024];
__device__ __align__(16) float g_Wann[256 * 1024];
__device__ __align__(16) float g_Wx[256 * 768];
__device__ __align__(16) float g_annprojB[2048 * 256]; // [(b*S+s)][256]  (+b1)
__device__ __align__(16) float g_annWi[2048 * 768];    // [(b*S+s)][768]
__device__ __align__(16) float g_xproj[2048 * 768];    // [(t*B+b)][768]  (+bi*)
__device__ __align__(16) __half g_Ah[2048 * 512];      // [A_hi(256)|A_lo(256)]
__device__ __align__(16) __half g_Bh[32000L * 256];    // B_hi, K-major

// ---------------------------------------------------------------------------
// K0: build fused weight matrices
// ---------------------------------------------------------------------------
__global__ void prep_kernel(const float* __restrict__ W1,
                            const float* __restrict__ Wiz, const float* __restrict__ Wir,
                            const float* __restrict__ Wih,
                            const float* __restrict__ Whz, const float* __restrict__ bhz,
                            const float* __restrict__ Whr, const float* __restrict__ bhr,
                            const float* __restrict__ Whh, const float* __restrict__ bhh) {
    int idx = blockIdx.x * blockDim.x + threadIdx.x;
    int stride = gridDim.x * blockDim.x;
    for (int i = idx; i < 256 * 1024; i += stride) {
        int k = i >> 10, j = i & 1023;
        float wc, wa;
        if (j < 256)      { wc = W1[k * 256 + j];          wa = W1[(256 + k) * 256 + j]; }
        else if (j < 512) { wc = Whz[k * 256 + j - 256];   wa = Wiz[k * 256 + j - 256]; }
        else if (j < 768) { wc = Whr[k * 256 + j - 512];   wa = Wir[k * 256 + j - 512]; }
        else              { wc = Whh[k * 256 + j - 768];   wa = Wih[k * 256 + j - 768]; }
        g_Wcat[i] = wc; g_Wann[i] = wa;
    }
    for (int i = idx; i < 256 * 768; i += stride) {
        int k = i / 768, j = i % 768;
        float w;
        if (j < 256)      w = Wiz[(256 + k) * 256 + j];
        else if (j < 512) w = Wir[(256 + k) * 256 + j - 256];
        else              w = Wih[(256 + k) * 256 + j - 512];
        g_Wx[i] = w;
    }
    for (int i = idx; i < 1024; i += stride) {
        float bv = 0.f;
        if (i >= 256 && i < 512)      bv = bhz[i - 256];
        else if (i >= 512 && i < 768) bv = bhr[i - 512];
        else if (i >= 768)            bv = bhh[i - 768];
        g_bcat[i] = bv;
    }
}

// ---------------------------------------------------------------------------
// K1 combo: sgemm mode1 (512 CTAs) + sgemm mode2 (384) + Wout->fp16 (4000)
// ---------------------------------------------------------------------------
__global__ void __launch_bounds__(128)
combo_kernel(const float* __restrict__ ann, const float* __restrict__ emb,
             const int* __restrict__ inputs, const float* __restrict__ Wout,
             const float* __restrict__ b1, const float* __restrict__ biz,
             const float* __restrict__ bir, const float* __restrict__ bih) {
    __shared__ __align__(16) float sm[2][64 * 20 + 16 * 68];
    __shared__ __align__(16) float sw[32 * 68];
    __shared__ int tok[64];

    const int bid = blockIdx.x, tid = threadIdx.x;

    if (bid >= 896) {
        int b3 = bid - 896;
        int k0 = (b3 & 7) * 32, n0 = (b3 >> 3) * 64;
        for (int i = tid; i < 32 * 64; i += 128) {
            int k = i >> 6, n = i & 63;
            sw[k * 68 + n] = Wout[(size_t)(k0 + k) * VV + n0 + n];
        }
        __syncthreads();
        const int n = tid >> 1, kh = (tid & 1) * 16;
        __align__(16) __half vals[16];
#pragma unroll
        for (int j = 0; j < 16; j++) vals[j] = __float2half(sw[(kh + j) * 68 + n]);
        __half* dst = g_Bh + (size_t)(n0 + n) * 256 + k0 + kh;
        *(uint4*)dst       = ((const uint4*)vals)[0];
        *(uint4*)(dst + 8) = ((const uint4*)vals)[1];
        return;
    }

    const bool m1 = bid < 512;
    int row0, col0, N;
    const float* Bm;
    if (m1) { row0 = (bid >> 4) * 64; col0 = (bid & 15) * 64; N = 1024; Bm = g_Wann; }
    else    { int b2 = bid - 512; row0 = (b2 / 12) * 64; col0 = (b2 % 12) * 64; N = 768; Bm = g_Wx; }

    if (!m1 && tid < 64) {
        int r = row0 + tid;
        tok[tid] = inputs[(r & 31) * TT + (r >> 5)];
    }
    if (!m1) __syncthreads();

    const int rA = tid >> 2, kqA = (tid & 3) * 4;
    const int kB = tid >> 4, nB = (tid & 15) * 4;
    const float* ArowA = m1 ? (ann + (size_t)(row0 + rA) * 256)
                            : (emb + (size_t)tok[rA] * 256);
    const float* ArowB = m1 ? (ann + (size_t)(row0 + rA + 32) * 256)
                            : (emb + (size_t)tok[rA + 32] * 256);
    const float* Bcol = Bm + col0;

    {
        float4 a0 = *(const float4*)(ArowA + kqA);
        float4 a1 = *(const float4*)(ArowB + kqA);
        float4 b0 = *(const float4*)(Bcol + (size_t)kB * N + nB);
        float4 b1v = *(const float4*)(Bcol + (size_t)(kB + 8) * N + nB);
        *(float4*)&sm[0][rA * 20 + kqA]        = a0;
        *(float4*)&sm[0][(rA + 32) * 20 + kqA] = a1;
        *(float4*)&sm[0][1280 + kB * 68 + nB]        = b0;
        *(float4*)&sm[0][1280 + (kB + 8) * 68 + nB]  = b1v;
    }
    __syncthreads();

    float acc[4][8];
#pragma unroll
    for (int i = 0; i < 4; i++)
#pragma unroll
        for (int j = 0; j < 8; j++) acc[i][j] = 0.f;

    const int ty4 = (tid >> 3) * 4, tx8 = (tid & 7) * 8;
    int buf = 0;

#pragma unroll 1
    for (int kt = 0; kt < 16; kt++) {
        float4 nA0, nA1, nB0, nB1;
        if (kt < 15) {
            int k0 = (kt + 1) * 16;
            nA0 = *(const float4*)(ArowA + k0 + kqA);
            nA1 = *(const float4*)(ArowB + k0 + kqA);
            nB0 = *(const float4*)(Bcol + (size_t)(k0 + kB) * N + nB);
            nB1 = *(const float4*)(Bcol + (size_t)(k0 + kB + 8) * N + nB);
        }
        const float* As_ = &sm[buf][0];
        const float* Bs_ = &sm[buf][1280];
#pragma unroll
        for (int kk = 0; kk < 16; kk++) {
            float a[4], b[8];
#pragma unroll
            for (int i = 0; i < 4; i++) a[i] = As_[(ty4 + i) * 20 + kk];
            *(float4*)&b[0] = *(const float4*)&Bs_[kk * 68 + tx8];
            *(float4*)&b[4] = *(const float4*)&Bs_[kk * 68 + tx8 + 4];
#pragma unroll
            for (int i = 0; i < 4; i++)
#pragma unroll
                for (int j = 0; j < 8; j++) acc[i][j] += a[i] * b[j];
        }
        if (kt < 15) {
            buf ^= 1;
            __syncthreads();
            *(float4*)&sm[buf][rA * 20 + kqA]        = nA0;
            *(float4*)&sm[buf][(rA + 32) * 20 + kqA] = nA1;
            *(float4*)&sm[buf][1280 + kB * 68 + nB]        = nB0;
            *(float4*)&sm[buf][1280 + (kB + 8) * 68 + nB]  = nB1;
            __syncthreads();
        }
    }

#pragma unroll
    for (int i = 0; i < 4; i++) {
        int r = row0 + ty4 + i;
#pragma unroll
        for (int j = 0; j < 8; j++) {
            int cidx = col0 + tx8 + j;
            float v = acc[i][j];
            if (m1) {
                if (cidx < 256) g_annprojB[(size_t)r * 256 + cidx] = v + b1[cidx];
                else            g_annWi[(size_t)r * 768 + (cidx - 256)] = v;
            } else {
                float bv = (cidx < 256) ? biz[cidx]
                         : (cidx < 512) ? bir[cidx - 256] : bih[cidx - 512];
                g_xproj[(size_t)r * 768 + cidx] = v + bv;
            }
        }
    }
}

// ---------------------------------------------------------------------------
// K3: clustered recurrence. 16 clusters x 8 CTAs; cluster owns 2 batches.
// CTA rank q owns hcat cols [q*128,(q+1)*128): q0/1 qproj, q2/3 z, q4/5 r, q6/7 hbar.
// Weights SMEM-resident; only cluster barriers (no grid barrier).
// ---------------------------------------------------------------------------
// dsm float offsets
#define O_WS   0        // 128 x 260 (weights, transposed, padded)
#define O_TILE 33280    // 2 x 64 x 132 (annproj slice for q<2, annWi slice else)
#define O_HS   50176    // 2 x 256 hidden state
#define O_HC   50688    // 2 x 128 hcat slice
#define O_UP   50944    // 2 x 128 logit-part hub (rank 0)
#define O_UPP  51200    // 256 local logit partials
#define O_AL   51456    // 2 x 64 alpha
#define O_GS   51584    // 2 x 128 gate sums / hbar linear
#define O_ZR   51840    // z[256] | r[256] (ranks 6,7 receive)
#define O_BS   52352    // 128 bias slice
#define O_W2   52480    // 256
#define REC_DSMEM (52736 * 4)

__global__ void __launch_bounds__(256, 1) __cluster_dims__(8, 1, 1)
recurrence_kernel(const float* __restrict__ hidden_init,
                  const float* __restrict__ W2,
                  float* __restrict__ att_out) {
    extern __shared__ __align__(16) float dsm[];
    __shared__ float red_m[4], red_s[4];

    const int tid = threadIdx.x;
    const uint32_t q = ctarank();
    const int cl = blockIdx.x >> 3;
    const int b0 = cl * 2;
    const int colbase = (int)q * 128;
    const uint32_t sbase = smem_u32(dsm);

    // ---- init: weights (transposed, pitch 260), bias, W2, tile, h ----
    for (int i = tid; i < 128 * 256; i += 256) {
        int j = i >> 8, k = i & 255;
        dsm[O_WS + j * 260 + k] = g_Wcat[k * 1024 + colbase + j];
    }
    if (tid < 128) dsm[O_BS + tid] = g_bcat[colbase + tid];
    dsm[O_W2 + tid] = W2[tid];
    for (int i = tid; i < 2 * 64 * 128; i += 256) {
        int bb = i >> 13, rem = i & 8191;
        int s = rem >> 7, cloc = rem & 127;
        float v;
        if (q < 2) v = g_annprojB[(size_t)((b0 + bb) * 64 + s) * 256 + colbase + cloc];
        else       v = g_annWi[(size_t)((b0 + bb) * 64 + s) * 768 + (colbase - 256) + cloc];
        dsm[O_TILE + bb * 8448 + s * 132 + cloc] = v;
    }
    for (int i = tid; i < 512; i += 256)
        dsm[O_HS + i] = hidden_init[(b0 + (i >> 8)) * 256 + (i & 255)];
    __syncthreads();
    CLUSTER_SYNC();

    const int bbT = tid >> 7, jT = tid & 127;   // hcat map
    const int khL = tid >> 7, subL = tid & 127; // logit map
    const int bbL = subL >> 6, sL = subL & 63;

#pragma unroll 1
    for (int t = 0; t < TT; t++) {
        // ---- (1) hcat slice: hc[bb][j] = bias + h[bb] . w[:,j] ----
        {
            float a = dsm[O_BS + jT];
            const float* hp = &dsm[O_HS + bbT * 256];
            const float* wp = &dsm[O_WS + jT * 260];
#pragma unroll
            for (int k = 0; k < 256; k += 4) {
                float4 hv = *(const float4*)(hp + k);
                float4 wv = *(const float4*)(wp + k);
                a += hv.x * wv.x + hv.y * wv.y + hv.z * wv.z + hv.w * wv.w;
            }
            dsm[O_HC + bbT * 128 + jT] = a;
        }
        __syncthreads();

        // ---- (2) attention logit partials (q=0,1) ----
        if (q < 2) {
            float p = 0.f;
            const float* qp = &dsm[O_HC + bbL * 128];
            const float* ap = &dsm[O_TILE + bbL * 8448 + sL * 132];
            const float* wp2 = &dsm[O_W2 + colbase];
#pragma unroll
            for (int c = khL * 64; c < khL * 64 + 64; c += 4) {
                float4 qv = *(const float4*)(qp + c);
                float4 av = *(const float4*)(ap + c);
                float4 wv = *(const float4*)(wp2 + c);
                p += wv.x * fmaxf(qv.x + av.x, 0.f) + wv.y * fmaxf(qv.y + av.y, 0.f)
                   + wv.z * fmaxf(qv.z + av.z, 0.f) + wv.w * fmaxf(qv.w + av.w, 0.f);
            }
            dsm[O_UPP + khL * 128 + subL] = p;
            __syncthreads();
            if (tid < 128) {
                float u = dsm[O_UPP + tid] + dsm[O_UPP + 128 + tid];
                if (q == 0) {
                    dsm[O_UP + tid] = u;
                } else {
                    uint32_t ra = mapa_u32(sbase + (O_UP + 128 + tid) * 4, 0);
                    st_cluster_f32(ra, u);
                }
            }
        }
        CLUSTER_SYNC();  // sync1: hub has both logit parts

        // ---- (3) softmax (redundant per consumer CTA) ----
        float u_v = 0.f, e_v = 0.f;
        if (tid < 128 && (q == 0 || q >= 2)) {
            if (q == 0) {
                u_v = dsm[O_UP + tid] + dsm[O_UP + 128 + tid];
            } else {
                uint32_t r0a = mapa_u32(sbase + (O_UP + tid) * 4, 0);
                uint32_t r1a = mapa_u32(sbase + (O_UP + 128 + tid) * 4, 0);
                u_v = ld_cluster_f32(r0a) + ld_cluster_f32(r1a);
            }
            float m = u_v;
#pragma unroll
            for (int o = 16; o; o >>= 1) m = fmaxf(m, __shfl_xor_sync(0xffffffffu, m, o));
            if ((tid & 31) == 0) red_m[tid >> 5] = m;
        }
        __syncthreads();
        if (tid < 128 && (q == 0 || q >= 2)) {
            int bb = tid >> 6;
            float m = fmaxf(red_m[bb * 2], red_m[bb * 2 + 1]);
            e_v = __expf(u_v - m);
            float sum = e_v;
#pragma unroll
            for (int o = 16; o; o >>= 1) sum += __shfl_xor_sync(0xffffffffu, sum, o);
            if ((tid & 31) == 0) red_s[tid >> 5] = sum;
        }
        __syncthreads();
        if (tid < 128 && (q == 0 || q >= 2)) {
            int bb = tid >> 6, s = tid & 63;
            float inv = 1.f / (red_s[bb * 2] + red_s[bb * 2 + 1]);
            float al = e_v * inv;
            dsm[O_AL + tid] = al;
            if (q == 0) att_out[((b0 + bb) * SS + s) * TT + t] = al;
        }
        __syncthreads();

        // ---- (4) gate sums + activation + push (q>=2) ----
        if (q >= 2) {
            if (tid < 64) {
                int bb = tid >> 5, d = (tid & 31) * 4;
                const float* alp = &dsm[O_AL + bb * 64];
                const float* tp = &dsm[O_TILE + bb * 8448];
                float4 acc = make_float4(0.f, 0.f, 0.f, 0.f);
#pragma unroll 8
                for (int s = 0; s < 64; s++) {
                    float w = alp[s];
                    float4 v = *(const float4*)(tp + s * 132 + d);
                    acc.x += w * v.x; acc.y += w * v.y;
                    acc.z += w * v.z; acc.w += w * v.w;
                }
                *(float4*)&dsm[O_GS + bb * 128 + d] = acc;
            }
            __syncthreads();
            {
                int bb = tid >> 7, dl = tid & 127;
                float pre = dsm[O_GS + bb * 128 + dl]
                          + g_xproj[(size_t)(t * 32 + b0 + bb) * 768 + (colbase - 256) + dl];
                if (q < 6) {
                    float v = 1.f / (1.f + __expf(-(pre + dsm[O_HC + bb * 128 + dl])));
                    int zr_off = (q < 4) ? 0 : 256;
                    uint32_t ra = mapa_u32(sbase + (O_ZR + zr_off + bb * 128 + dl) * 4,
                                           6 + (q & 1));
                    st_cluster_f32(ra, v);
                } else {
                    dsm[O_GS + bb * 128 + dl] = pre;  // hbar linear part
                }
            }
        }
        CLUSTER_SYNC();  // sync2: z, r delivered to ranks 6/7

        // ---- (5) GRU combine + h broadcast (q=6,7) ----
        if (q >= 6) {
            int bb = tid >> 7, dl = tid & 127;
            int dg = (int)(q - 6) * 128 + dl;
            float z = dsm[O_ZR + bb * 128 + dl];
            float r = dsm[O_ZR + 256 + bb * 128 + dl];
            float g = tanhf(dsm[O_GS + bb * 128 + dl] + r * dsm[O_HC + bb * 128 + dl]);
            float hold = dsm[O_HS + bb * 256 + dg];
            float hn = (1.f - z) * g + z * hold;
            uint32_t laddr = sbase + (O_HS + bb * 256 + dg) * 4;
#pragma unroll
            for (int rk = 0; rk < 8; rk++)
                st_cluster_f32(mapa_u32(laddr, rk), hn);
            __half hi = __float2half(hn);
            __half lo = __float2half(hn - __half2float(hi));
            size_t rb = (size_t)((b0 + bb) * 64 + t) * 512;
            g_Ah[rb + dg]       = hi;
            g_Ah[rb + 256 + dg] = lo;
        }
        CLUSTER_SYNC();  // sync3: new h visible everywhere
    }
}

// ---------------------------------------------------------------------------
// K4: HMMA fp16 GEMM (R4 version): D[2048,32000] = Ah[2048,512] @ Bh^T
// tile 128x128, BK=32, 16 k-chunks (B chunk = kt&7), 3-stage cp.async
// ---------------------------------------------------------------------------
#define GSTAGES 3

__global__ void __launch_bounds__(256, 2)
gemm_mma_kernel(const float* __restrict__ bout, float* __restrict__ out) {
    __shared__ __align__(128) __half sA[GSTAGES][128 * 32];
    __shared__ __align__(128) __half sB[GSTAGES][128 * 32];

    const int tid  = threadIdx.x;
    const int lane = tid & 31, wid = tid >> 5;
    const int wr = wid >> 2, wc = wid & 3;
    const int row0 = blockIdx.x * 128, col0 = blockIdx.y * 128;

    const __half* Ag = g_Ah + (size_t)row0 * 512;
    const __half* Bg = g_Bh + (size_t)col0 * 256;

    const uint32_t sAb = smem_u32(sA);
    const uint32_t sBb = smem_u32(sB);

    const int rA0 = tid >> 2,          cA0 = tid & 3;
    const int rA1 = (tid + 256) >> 2;
    const uint32_t dA0 = rA0 * 64 + ((cA0 ^ ((rA0 >> 1) & 3)) * 16);
    const uint32_t dA1 = rA1 * 64 + ((cA0 ^ ((rA1 >> 1) & 3)) * 16);

#define LOAD_STAGE(s, kt) do {                                                       \
        uint32_t ab = sAb + (s) * 8192, bb = sBb + (s) * 8192;                       \
        int bk = ((kt) & 7) * 32;                                                    \
        cp_async16(ab + dA0, Ag + (size_t)rA0 * 512 + (kt) * 32 + cA0 * 8);          \
        cp_async16(ab + dA1, Ag + (size_t)rA1 * 512 + (kt) * 32 + cA0 * 8);          \
        cp_async16(bb + dA0, Bg + (size_t)rA0 * 256 + bk + cA0 * 8);                 \
        cp_async16(bb + dA1, Bg + (size_t)rA1 * 256 + bk + cA0 * 8);                 \
    } while (0)

    LOAD_STAGE(0, 0); CP_COMMIT();
    LOAD_STAGE(1, 1); CP_COMMIT();

    float acc[4][4][4];
#pragma unroll
    for (int i = 0; i < 4; i++)
#pragma unroll
        for (int j = 0; j < 4; j++)
#pragma unroll
            for (int q = 0; q < 4; q++) acc[i][j][q] = 0.f;

    const int aRow = lane & 15;
    const int aSel = lane >> 4;
    const int bRow = (lane & 7) + ((lane >> 4) << 3);
    const int bSel = (lane >> 3) & 1;

#pragma unroll 1
    for (int kt = 0; kt < 16; kt++) {
        CP_WAIT(1);
        __syncthreads();
        if (kt + 2 < 16) LOAD_STAGE((kt + 2) % GSTAGES, kt + 2);
        CP_COMMIT();

        const int st = kt % GSTAGES;
        const uint32_t ab = sAb + st * 8192;
        const uint32_t bb = sBb + st * 8192;

#pragma unroll
        for (int kf = 0; kf < 2; kf++) {
            uint32_t aF[4][4];
#pragma unroll
            for (int mf = 0; mf < 4; mf++) {
                int row = wr * 64 + mf * 16 + aRow;
                int ch  = (kf * 2 + aSel) ^ ((row >> 1) & 3);
                ldsm_x4(ab + row * 64 + ch * 16, aF[mf][0], aF[mf][1], aF[mf][2], aF[mf][3]);
            }
            uint32_t bF[2][4];
#pragma unroll
            for (int nf2 = 0; nf2 < 2; nf2++) {
                int row = wc * 32 + nf2 * 16 + bRow;
                int ch  = (kf * 2 + bSel) ^ ((row >> 1) & 3);
                ldsm_x4(bb + row * 64 + ch * 16, bF[nf2][0], bF[nf2][1], bF[nf2][2], bF[nf2][3]);
            }
#pragma unroll
            for (int mf = 0; mf < 4; mf++)
#pragma unroll
                for (int nf = 0; nf < 4; nf++) {
                    uint32_t b0 = bF[nf >> 1][(nf & 1) * 2 + 0];
                    uint32_t b1 = bF[nf >> 1][(nf & 1) * 2 + 1];
                    mma16816(acc[mf][nf], aF[mf], b0, b1);
                }
        }
        __syncthreads();
    }

    const int rq = lane >> 2, cq = (lane & 3) * 2;
    const int rbase = row0 + wr * 64, cbase = col0 + wc * 32;
#pragma unroll
    for (int mf = 0; mf < 4; mf++) {
#pragma unroll
        for (int nf = 0; nf < 4; nf++) {
            int r  = rbase + mf * 16 + rq;
            int cc = cbase + nf * 8 + cq;
            float bz0 = bout[cc], bz1 = bout[cc + 1];
            float2 v0 = make_float2(acc[mf][nf][0] + bz0, acc[mf][nf][1] + bz1);
            float2 v1 = make_float2(acc[mf][nf][2] + bz0, acc[mf][nf][3] + bz1);
            *(float2*)&out[(size_t)r * VV + cc]       = v0;
            *(float2*)&out[(size_t)(r + 8) * VV + cc] = v1;
        }
    }
#undef LOAD_STAGE
}

// ---------------------------------------------------------------------------
extern "C" void kernel_launch(void* const* d_in, const int* in_sizes, int n_in,
                              void* d_out, int out_size) {
    const int*   inputs = (const int*)  d_in[0];
    const float* ann    = (const float*)d_in[1];
    const float* hinit  = (const float*)d_in[2];
    const float* emb    = (const float*)d_in[3];
    const float* W1     = (const float*)d_in[4];
    const float* b1     = (const float*)d_in[5];
    const float* W2     = (const float*)d_in[6];
    /* b2 (d_in[7]) cancels in softmax */
    const float* Wiz    = (const float*)d_in[8];
    const float* biz    = (const float*)d_in[9];
    const float* Wir    = (const float*)d_in[10];
    const float* bir    = (const float*)d_in[11];
    const float* Wih    = (const float*)d_in[12];
    const float* bih    = (const float*)d_in[13];
    const float* Whz    = (const float*)d_in[14];
    const float* bhz    = (const float*)d_in[15];
    const float* Whr    = (const float*)d_in[16];
    const float* bhr    = (const float*)d_in[17];
    const float* Whh    = (const float*)d_in[18];
    const float* bhh    = (const float*)d_in[19];
    const float* Wout   = (const float*)d_in[20];
    const float* bout   = (const float*)d_in[21];

    float* out = (float*)d_out;
    float* att = out + (size_t)BB * TT * VV;

    static int attr_set = 0;
    if (!attr_set) {
        cudaFuncSetAttribute(recurrence_kernel,
                             cudaFuncAttributeMaxDynamicSharedMemorySize, REC_DSMEM);
        attr_set = 1;
    }

    prep_kernel<<<256, 256>>>(W1, Wiz, Wir, Wih, Whz, bhz, Whr, bhr, Whh, bhh);
    combo_kernel<<<4896, 128>>>(ann, emb, inputs, Wout, b1, biz, bir, bih);
    recurrence_kernel<<<128, 256, REC_DSMEM>>>(hinit, W2, att);
    gemm_mma_kernel<<<dim3(16, 250), 256>>>(bout, out);
}

// round 7
// speedup vs baseline: 1.2796x; 1.2580x over previous
#include <cuda_runtime.h>
#include <cuda_fp16.h>
#include <cstdint>

// Problem constants
#define BB   32
#define TT   64
#define SS   64
#define HH   256
#define VV   32000

// ---------------------------------------------------------------------------
// PTX helpers
// ---------------------------------------------------------------------------
__device__ __forceinline__ uint32_t smem_u32(const void* p) {
    uint32_t a;
    asm("{ .reg .u64 t; cvta.to.shared.u64 t, %1; cvt.u32.u64 %0, t; }" : "=r"(a) : "l"(p));
    return a;
}
__device__ __forceinline__ void cp_async16(uint32_t dst, const void* src) {
    asm volatile("cp.async.cg.shared.global [%0], [%1], 16;" :: "r"(dst), "l"(src));
}
#define CP_COMMIT() asm volatile("cp.async.commit_group;" ::: "memory")
#define CP_WAIT(n)  asm volatile("cp.async.wait_group %0;" :: "n"(n) : "memory")

__device__ __forceinline__ void ldsm_x4(uint32_t addr, uint32_t& r0, uint32_t& r1,
                                        uint32_t& r2, uint32_t& r3) {
    asm volatile("ldmatrix.sync.aligned.m8n8.x4.shared.b16 {%0,%1,%2,%3}, [%4];"
                 : "=r"(r0), "=r"(r1), "=r"(r2), "=r"(r3) : "r"(addr));
}
__device__ __forceinline__ void mma16816(float* c, const uint32_t* a,
                                         uint32_t b0, uint32_t b1) {
    asm volatile("mma.sync.aligned.m16n8k16.row.col.f32.f16.f16.f32 "
                 "{%0,%1,%2,%3}, {%4,%5,%6,%7}, {%8,%9}, {%0,%1,%2,%3};"
                 : "+f"(c[0]), "+f"(c[1]), "+f"(c[2]), "+f"(c[3])
                 : "r"(a[0]), "r"(a[1]), "r"(a[2]), "r"(a[3]), "r"(b0), "r"(b1));
}
__device__ __forceinline__ uint32_t ctarank() {
    uint32_t r; asm("mov.u32 %0, %%cluster_ctarank;" : "=r"(r)); return r;
}
__device__ __forceinline__ uint32_t mapa_u32(uint32_t laddr, uint32_t rank) {
    uint32_t r;
    asm("mapa.shared::cluster.u32 %0, %1, %2;" : "=r"(r) : "r"(laddr), "r"(rank));
    return r;
}
__device__ __forceinline__ void st_cluster_f32(uint32_t addr, float v) {
    asm volatile("st.shared::cluster.f32 [%0], %1;" :: "r"(addr), "f"(v) : "memory");
}
#define CLUSTER_SYNC() do { \
    asm volatile("barrier.cluster.arrive.aligned;" ::: "memory"); \
    asm volatile("barrier.cluster.wait.aligned;" ::: "memory"); \
} while (0)

// ---------------------------------------------------------------------------
// Device scratch
// ---------------------------------------------------------------------------
__device__ __align__(16) float g_Wcat[256 * 1024];     // [k][qproj|Whz|Whr|Whh]
__device__ __align__(16) float g_bcat[1024];
__device__ __align__(16) float g_Wann[256 * 1024];
__device__ __align__(16) float g_Wx[256 * 768];
__device__ __align__(16) float g_annprojB[2048 * 256]; // [(b*S+s)][256]  (+b1)
__device__ __align__(16) float g_annWi[2048 * 768];    // [(b*S+s)][768]
__device__ __align__(16) float g_xproj[2048 * 768];    // [(t*B+b)][768]  (+bi*)
__device__ __align__(16) __half g_Ah[2048 * 512];      // [A_hi(256)|A_lo(256)]
__device__ __align__(16) __half g_Bh[32000L * 256];    // B_hi, K-major

// ---------------------------------------------------------------------------
// K0: build fused weight matrices
// ---------------------------------------------------------------------------
__global__ void prep_kernel(const float* __restrict__ W1,
                            const float* __restrict__ Wiz, const float* __restrict__ Wir,
                            const float* __restrict__ Wih,
                            const float* __restrict__ Whz, const float* __restrict__ bhz,
                            const float* __restrict__ Whr, const float* __restrict__ bhr,
                            const float* __restrict__ Whh, const float* __restrict__ bhh) {
    int idx = blockIdx.x * blockDim.x + threadIdx.x;
    int stride = gridDim.x * blockDim.x;
    for (int i = idx; i < 256 * 1024; i += stride) {
        int k = i >> 10, j = i & 1023;
        float wc, wa;
        if (j < 256)      { wc = W1[k * 256 + j];          wa = W1[(256 + k) * 256 + j]; }
        else if (j < 512) { wc = Whz[k * 256 + j - 256];   wa = Wiz[k * 256 + j - 256]; }
        else if (j < 768) { wc = Whr[k * 256 + j - 512];   wa = Wir[k * 256 + j - 512]; }
        else              { wc = Whh[k * 256 + j - 768];   wa = Wih[k * 256 + j - 768]; }
        g_Wcat[i] = wc; g_Wann[i] = wa;
    }
    for (int i = idx; i < 256 * 768; i += stride) {
        int k = i / 768, j = i % 768;
        float w;
        if (j < 256)      w = Wiz[(256 + k) * 256 + j];
        else if (j < 512) w = Wir[(256 + k) * 256 + j - 256];
        else              w = Wih[(256 + k) * 256 + j - 512];
        g_Wx[i] = w;
    }
    for (int i = idx; i < 1024; i += stride) {
        float bv = 0.f;
        if (i >= 256 && i < 512)      bv = bhz[i - 256];
        else if (i >= 512 && i < 768) bv = bhr[i - 512];
        else if (i >= 768)            bv = bhh[i - 768];
        g_bcat[i] = bv;
    }
}

// ---------------------------------------------------------------------------
// K1 combo: sgemm mode1 (512 CTAs) + sgemm mode2 (384) + Wout->fp16 (4000)
// ---------------------------------------------------------------------------
__global__ void __launch_bounds__(128)
combo_kernel(const float* __restrict__ ann, const float* __restrict__ emb,
             const int* __restrict__ inputs, const float* __restrict__ Wout,
             const float* __restrict__ b1, const float* __restrict__ biz,
             const float* __restrict__ bir, const float* __restrict__ bih) {
    __shared__ __align__(16) float sm[2][64 * 20 + 16 * 68];
    __shared__ __align__(16) float sw[32 * 68];
    __shared__ int tok[64];

    const int bid = blockIdx.x, tid = threadIdx.x;

    if (bid >= 896) {
        int b3 = bid - 896;
        int k0 = (b3 & 7) * 32, n0 = (b3 >> 3) * 64;
        for (int i = tid; i < 32 * 64; i += 128) {
            int k = i >> 6, n = i & 63;
            sw[k * 68 + n] = Wout[(size_t)(k0 + k) * VV + n0 + n];
        }
        __syncthreads();
        const int n = tid >> 1, kh = (tid & 1) * 16;
        __align__(16) __half vals[16];
#pragma unroll
        for (int j = 0; j < 16; j++) vals[j] = __float2half(sw[(kh + j) * 68 + n]);
        __half* dst = g_Bh + (size_t)(n0 + n) * 256 + k0 + kh;
        *(uint4*)dst       = ((const uint4*)vals)[0];
        *(uint4*)(dst + 8) = ((const uint4*)vals)[1];
        return;
    }

    const bool m1 = bid < 512;
    int row0, col0, N;
    const float* Bm;
    if (m1) { row0 = (bid >> 4) * 64; col0 = (bid & 15) * 64; N = 1024; Bm = g_Wann; }
    else    { int b2 = bid - 512; row0 = (b2 / 12) * 64; col0 = (b2 % 12) * 64; N = 768; Bm = g_Wx; }

    if (!m1 && tid < 64) {
        int r = row0 + tid;
        tok[tid] = inputs[(r & 31) * TT + (r >> 5)];
    }
    if (!m1) __syncthreads();

    const int rA = tid >> 2, kqA = (tid & 3) * 4;
    const int kB = tid >> 4, nB = (tid & 15) * 4;
    const float* ArowA = m1 ? (ann + (size_t)(row0 + rA) * 256)
                            : (emb + (size_t)tok[rA] * 256);
    const float* ArowB = m1 ? (ann + (size_t)(row0 + rA + 32) * 256)
                            : (emb + (size_t)tok[rA + 32] * 256);
    const float* Bcol = Bm + col0;

    {
        float4 a0 = *(const float4*)(ArowA + kqA);
        float4 a1 = *(const float4*)(ArowB + kqA);
        float4 b0 = *(const float4*)(Bcol + (size_t)kB * N + nB);
        float4 b1v = *(const float4*)(Bcol + (size_t)(kB + 8) * N + nB);
        *(float4*)&sm[0][rA * 20 + kqA]        = a0;
        *(float4*)&sm[0][(rA + 32) * 20 + kqA] = a1;
        *(float4*)&sm[0][1280 + kB * 68 + nB]        = b0;
        *(float4*)&sm[0][1280 + (kB + 8) * 68 + nB]  = b1v;
    }
    __syncthreads();

    float acc[4][8];
#pragma unroll
    for (int i = 0; i < 4; i++)
#pragma unroll
        for (int j = 0; j < 8; j++) acc[i][j] = 0.f;

    const int ty4 = (tid >> 3) * 4, tx8 = (tid & 7) * 8;
    int buf = 0;

#pragma unroll 1
    for (int kt = 0; kt < 16; kt++) {
        float4 nA0, nA1, nB0, nB1;
        if (kt < 15) {
            int k0 = (kt + 1) * 16;
            nA0 = *(const float4*)(ArowA + k0 + kqA);
            nA1 = *(const float4*)(ArowB + k0 + kqA);
            nB0 = *(const float4*)(Bcol + (size_t)(k0 + kB) * N + nB);
            nB1 = *(const float4*)(Bcol + (size_t)(k0 + kB + 8) * N + nB);
        }
        const float* As_ = &sm[buf][0];
        const float* Bs_ = &sm[buf][1280];
#pragma unroll
        for (int kk = 0; kk < 16; kk++) {
            float a[4], b[8];
#pragma unroll
            for (int i = 0; i < 4; i++) a[i] = As_[(ty4 + i) * 20 + kk];
            *(float4*)&b[0] = *(const float4*)&Bs_[kk * 68 + tx8];
            *(float4*)&b[4] = *(const float4*)&Bs_[kk * 68 + tx8 + 4];
#pragma unroll
            for (int i = 0; i < 4; i++)
#pragma unroll
                for (int j = 0; j < 8; j++) acc[i][j] += a[i] * b[j];
        }
        if (kt < 15) {
            buf ^= 1;
            __syncthreads();
            *(float4*)&sm[buf][rA * 20 + kqA]        = nA0;
            *(float4*)&sm[buf][(rA + 32) * 20 + kqA] = nA1;
            *(float4*)&sm[buf][1280 + kB * 68 + nB]        = nB0;
            *(float4*)&sm[buf][1280 + (kB + 8) * 68 + nB]  = nB1;
            __syncthreads();
        }
    }

#pragma unroll
    for (int i = 0; i < 4; i++) {
        int r = row0 + ty4 + i;
#pragma unroll
        for (int j = 0; j < 8; j++) {
            int cidx = col0 + tx8 + j;
            float v = acc[i][j];
            if (m1) {
                if (cidx < 256) g_annprojB[(size_t)r * 256 + cidx] = v + b1[cidx];
                else            g_annWi[(size_t)r * 768 + (cidx - 256)] = v;
            } else {
                float bv = (cidx < 256) ? biz[cidx]
                         : (cidx < 512) ? bir[cidx - 256] : bih[cidx - 512];
                g_xproj[(size_t)r * 768 + cidx] = v + bv;
            }
        }
    }
}

// ---------------------------------------------------------------------------
// K3: clustered recurrence, BALANCED: rank q owns 32 cols of EACH gate block.
// 16 clusters x 8 CTAs x 2 batches. 2 cluster syncs per step.
// ---------------------------------------------------------------------------
// dsm float offsets
#define O_WS   0        // 128 rows x 260 (row: 0-31 qproj, 32-63 z, 64-95 r, 96-127 hbar)
#define O_TILE 33280    // 2 x 64 x 140 (col 0-31 annproj, 32-127 annWi z|r|h)
#define O_HS   51200    // 2 x 256 hidden state
#define O_HC   51712    // 2 x 128 hcat slice
#define O_UPA  51968    // 8 x 128 logit partials (received all-to-all)
#define O_AL   52992    // 2 x 64 alpha
#define O_ZR   53120    // 2 x 64 (z | r)
#define O_PHB  53248    // 2 x 32 hbar pre
#define O_XPS  53312    // 2 x 96 xproj slice (cp.async)
#define O_BS   53504    // 128 bias
#define O_W2   53632    // 32
#define REC_NF 53664
#define REC_DSMEM (REC_NF * 4)

__global__ void __launch_bounds__(256, 1) __cluster_dims__(8, 1, 1)
recurrence_kernel(const float* __restrict__ hidden_init,
                  const float* __restrict__ W2,
                  float* __restrict__ att_out) {
    extern __shared__ __align__(16) float dsm[];
    __shared__ float red_m[4], red_s[4];

    const int tid = threadIdx.x;
    const uint32_t q = ctarank();
    const int b0 = (blockIdx.x >> 3) * 2;
    const uint32_t sbase = smem_u32(dsm);

    // ---- init ----
    for (int i = tid; i < 128 * 256; i += 256) {
        int row = i >> 8, k = i & 255;
        int gcol = (row >> 5) * 256 + (int)q * 32 + (row & 31);
        dsm[O_WS + row * 260 + k] = g_Wcat[k * 1024 + gcol];
    }
    if (tid < 128) {
        int gcol = (tid >> 5) * 256 + (int)q * 32 + (tid & 31);
        dsm[O_BS + tid] = g_bcat[gcol];
    }
    if (tid < 32) dsm[O_W2 + tid] = W2[q * 32 + tid];
    for (int i = tid; i < 2 * 64 * 128; i += 256) {
        int bb = i >> 13, rem = i & 8191;
        int s = rem >> 7, c = rem & 127;
        float v;
        if (c < 32) {
            v = g_annprojB[(size_t)((b0 + bb) * 64 + s) * 256 + q * 32 + c];
        } else {
            int g = (c - 32) >> 5, jj = (c - 32) & 31;
            v = g_annWi[(size_t)((b0 + bb) * 64 + s) * 768 + g * 256 + q * 32 + jj];
        }
        dsm[O_TILE + (bb * 64 + s) * 140 + c] = v;
    }
    for (int i = tid; i < 512; i += 256)
        dsm[O_HS + i] = hidden_init[(b0 + (i >> 8)) * 256 + (i & 255)];
    __syncthreads();
    CLUSTER_SYNC();

#pragma unroll 1
    for (int t = 0; t < TT; t++) {
        // ---- (0) xproj prefetch (threads 128..175), (1) phase A (threads <128) ----
        if (tid >= 128 && tid < 176) {
            int idx = tid - 128;                   // 0..47
            int bb = idx / 24, rem = idx % 24;
            int g = rem >> 3, c8 = rem & 7;
            const float* src = g_xproj + (size_t)(t * 32 + b0 + bb) * 768
                             + g * 256 + q * 32 + c8 * 4;
            cp_async16(sbase + (O_XPS + bb * 96 + g * 32 + c8 * 4) * 4, src);
            CP_COMMIT();
        }
        if (tid < 128) {
            float a0 = dsm[O_BS + tid], a1 = a0;
            const float* wp = &dsm[O_WS + tid * 260];
            const float* h0 = &dsm[O_HS];
            const float* h1 = &dsm[O_HS + 256];
#pragma unroll
            for (int k = 0; k < 256; k += 4) {
                float4 w  = *(const float4*)(wp + k);
                float4 v0 = *(const float4*)(h0 + k);
                float4 v1 = *(const float4*)(h1 + k);
                a0 += w.x * v0.x + w.y * v0.y + w.z * v0.z + w.w * v0.w;
                a1 += w.x * v1.x + w.y * v1.y + w.z * v1.z + w.w * v1.w;
            }
            dsm[O_HC + tid]       = a0;
            dsm[O_HC + 128 + tid] = a1;
        }
        __syncthreads();

        // ---- (2) logit partials over this rank's 32 qproj cols ----
        {
            int p = tid >> 1, half = tid & 1;
            int bbL = p >> 6, sL = p & 63;
            const float* tp = &dsm[O_TILE + (bbL * 64 + sL) * 140];
            const float* hq = &dsm[O_HC + bbL * 128];
            const float* w2 = &dsm[O_W2];
            float u = 0.f;
#pragma unroll
            for (int m = 0; m < 4; m++) {
                int j = half * 16 + m * 4;
                float4 av = *(const float4*)(tp + j);
                float4 qv = *(const float4*)(hq + j);
                float4 wv = *(const float4*)(w2 + j);
                u += wv.x * fmaxf(qv.x + av.x, 0.f) + wv.y * fmaxf(qv.y + av.y, 0.f)
                   + wv.z * fmaxf(qv.z + av.z, 0.f) + wv.w * fmaxf(qv.w + av.w, 0.f);
            }
            u += __shfl_xor_sync(0xffffffffu, u, 1);
            if (!half) {
                uint32_t la = sbase + (O_UPA + (int)q * 128 + p) * 4;
#pragma unroll
                for (int rk = 0; rk < 8; rk++)
                    st_cluster_f32(mapa_u32(la, rk), u);
            }
        }
        CLUSTER_SYNC();  // sync1: all logit partials delivered everywhere

        // ---- (3) softmax (redundant per rank) ----
        float u_v = 0.f, e_v = 0.f;
        if (tid < 128) {
#pragma unroll
            for (int r = 0; r < 8; r++) u_v += dsm[O_UPA + r * 128 + tid];
            float m = u_v;
#pragma unroll
            for (int o = 16; o; o >>= 1) m = fmaxf(m, __shfl_xor_sync(0xffffffffu, m, o));
            if ((tid & 31) == 0) red_m[tid >> 5] = m;
        }
        __syncthreads();
        if (tid < 128) {
            int bb = tid >> 6;
            float m = fmaxf(red_m[bb * 2], red_m[bb * 2 + 1]);
            e_v = __expf(u_v - m);
            float sum = e_v;
#pragma unroll
            for (int o = 16; o; o >>= 1) sum += __shfl_xor_sync(0xffffffffu, sum, o);
            if ((tid & 31) == 0) red_s[tid >> 5] = sum;
        }
        __syncthreads();
        if (tid < 128) {
            int bb = tid >> 6, s = tid & 63;
            float inv = 1.f / (red_s[bb * 2] + red_s[bb * 2 + 1]);
            float al = e_v * inv;
            dsm[O_AL + tid] = al;
            if (q == 0) att_out[((b0 + bb) * SS + s) * TT + t] = al;
        }
        CP_WAIT(0);
        __syncthreads();

        // ---- (4) gate sums + activations (all local) ----
        if (tid < 192) {
            int bb = tid >= 96;
            int cc = 32 + tid - bb * 96;           // 32..127
            const float* tp = &dsm[O_TILE + bb * 64 * 140 + cc];
            const float* ap = &dsm[O_AL + bb * 64];
            float acc0 = 0.f, acc1 = 0.f;
#pragma unroll 8
            for (int s = 0; s < 64; s += 2) {
                acc0 += ap[s] * tp[s * 140];
                acc1 += ap[s + 1] * tp[(s + 1) * 140];
            }
            float pre = acc0 + acc1 + dsm[O_XPS + bb * 96 + cc - 32];
            if (cc < 96) {
                float v = 1.f / (1.f + __expf(-(pre + dsm[O_HC + bb * 128 + cc])));
                dsm[O_ZR + bb * 64 + cc - 32] = v;
            } else {
                dsm[O_PHB + bb * 32 + cc - 96] = pre;
            }
        }
        __syncthreads();

        // ---- (5) GRU combine (local dims) + h broadcast ----
        if (tid < 64) {
            int bb = tid >> 5, jj = tid & 31;
            int dg = (int)q * 32 + jj;
            float z = dsm[O_ZR + bb * 64 + jj];
            float r = dsm[O_ZR + bb * 64 + 32 + jj];
            float g = tanhf(dsm[O_PHB + bb * 32 + jj] + r * dsm[O_HC + bb * 128 + 96 + jj]);
            float hold = dsm[O_HS + bb * 256 + dg];
            float hn = (1.f - z) * g + z * hold;
            uint32_t la = sbase + (O_HS + bb * 256 + dg) * 4;
#pragma unroll
            for (int rk = 0; rk < 8; rk++)
                st_cluster_f32(mapa_u32(la, rk), hn);
            __half hi = __float2half(hn);
            __half lo = __float2half(hn - __half2float(hi));
            size_t rb = (size_t)((b0 + bb) * 64 + t) * 512;
            g_Ah[rb + dg]       = hi;
            g_Ah[rb + 256 + dg] = lo;
        }
        CLUSTER_SYNC();  // sync2: new h visible everywhere
    }
}

// ---------------------------------------------------------------------------
// K4: HMMA fp16 GEMM (unchanged from R4/R6 - 209us, tensor 53%)
// ---------------------------------------------------------------------------
#define GSTAGES 3

__global__ void __launch_bounds__(256, 2)
gemm_mma_kernel(const float* __restrict__ bout, float* __restrict__ out) {
    __shared__ __align__(128) __half sA[GSTAGES][128 * 32];
    __shared__ __align__(128) __half sB[GSTAGES][128 * 32];

    const int tid  = threadIdx.x;
    const int lane = tid & 31, wid = tid >> 5;
    const int wr = wid >> 2, wc = wid & 3;
    const int row0 = blockIdx.x * 128, col0 = blockIdx.y * 128;

    const __half* Ag = g_Ah + (size_t)row0 * 512;
    const __half* Bg = g_Bh + (size_t)col0 * 256;

    const uint32_t sAb = smem_u32(sA);
    const uint32_t sBb = smem_u32(sB);

    const int rA0 = tid >> 2,          cA0 = tid & 3;
    const int rA1 = (tid + 256) >> 2;
    const uint32_t dA0 = rA0 * 64 + ((cA0 ^ ((rA0 >> 1) & 3)) * 16);
    const uint32_t dA1 = rA1 * 64 + ((cA0 ^ ((rA1 >> 1) & 3)) * 16);

#define LOAD_STAGE(s, kt) do {                                                       \
        uint32_t ab = sAb + (s) * 8192, bb = sBb + (s) * 8192;                       \
        int bk = ((kt) & 7) * 32;                                                    \
        cp_async16(ab + dA0, Ag + (size_t)rA0 * 512 + (kt) * 32 + cA0 * 8);          \
        cp_async16(ab + dA1, Ag + (size_t)rA1 * 512 + (kt) * 32 + cA0 * 8);          \
        cp_async16(bb + dA0, Bg + (size_t)rA0 * 256 + bk + cA0 * 8);                 \
        cp_async16(bb + dA1, Bg + (size_t)rA1 * 256 + bk + cA0 * 8);                 \
    } while (0)

    LOAD_STAGE(0, 0); CP_COMMIT();
    LOAD_STAGE(1, 1); CP_COMMIT();

    float acc[4][4][4];
#pragma unroll
    for (int i = 0; i < 4; i++)
#pragma unroll
        for (int j = 0; j < 4; j++)
#pragma unroll
            for (int qq = 0; qq < 4; qq++) acc[i][j][qq] = 0.f;

    const int aRow = lane & 15;
    const int aSel = lane >> 4;
    const int bRow = (lane & 7) + ((lane >> 4) << 3);
    const int bSel = (lane >> 3) & 1;

#pragma unroll 1
    for (int kt = 0; kt < 16; kt++) {
        CP_WAIT(1);
        __syncthreads();
        if (kt + 2 < 16) LOAD_STAGE((kt + 2) % GSTAGES, kt + 2);
        CP_COMMIT();

        const int st = kt % GSTAGES;
        const uint32_t ab = sAb + st * 8192;
        const uint32_t bb = sBb + st * 8192;

#pragma unroll
        for (int kf = 0; kf < 2; kf++) {
            uint32_t aF[4][4];
#pragma unroll
            for (int mf = 0; mf < 4; mf++) {
                int row = wr * 64 + mf * 16 + aRow;
                int ch  = (kf * 2 + aSel) ^ ((row >> 1) & 3);
                ldsm_x4(ab + row * 64 + ch * 16, aF[mf][0], aF[mf][1], aF[mf][2], aF[mf][3]);
            }
            uint32_t bF[2][4];
#pragma unroll
            for (int nf2 = 0; nf2 < 2; nf2++) {
                int row = wc * 32 + nf2 * 16 + bRow;
                int ch  = (kf * 2 + bSel) ^ ((row >> 1) & 3);
                ldsm_x4(bb + row * 64 + ch * 16, bF[nf2][0], bF[nf2][1], bF[nf2][2], bF[nf2][3]);
            }
#pragma unroll
            for (int mf = 0; mf < 4; mf++)
#pragma unroll
                for (int nf = 0; nf < 4; nf++) {
                    uint32_t b0 = bF[nf >> 1][(nf & 1) * 2 + 0];
                    uint32_t b1 = bF[nf >> 1][(nf & 1) * 2 + 1];
                    mma16816(acc[mf][nf], aF[mf], b0, b1);
                }
        }
        __syncthreads();
    }

    const int rq = lane >> 2, cq = (lane & 3) * 2;
    const int rbase = row0 + wr * 64, cbase = col0 + wc * 32;
#pragma unroll
    for (int mf = 0; mf < 4; mf++) {
#pragma unroll
        for (int nf = 0; nf < 4; nf++) {
            int r  = rbase + mf * 16 + rq;
            int cc = cbase + nf * 8 + cq;
            float bz0 = bout[cc], bz1 = bout[cc + 1];
            float2 v0 = make_float2(acc[mf][nf][0] + bz0, acc[mf][nf][1] + bz1);
            float2 v1 = make_float2(acc[mf][nf][2] + bz0, acc[mf][nf][3] + bz1);
            *(float2*)&out[(size_t)r * VV + cc]       = v0;
            *(float2*)&out[(size_t)(r + 8) * VV + cc] = v1;
        }
    }
#undef LOAD_STAGE
}

// ---------------------------------------------------------------------------
extern "C" void kernel_launch(void* const* d_in, const int* in_sizes, int n_in,
                              void* d_out, int out_size) {
    const int*   inputs = (const int*)  d_in[0];
    const float* ann    = (const float*)d_in[1];
    const float* hinit  = (const float*)d_in[2];
    const float* emb    = (const float*)d_in[3];
    const float* W1     = (const float*)d_in[4];
    const float* b1     = (const float*)d_in[5];
    const float* W2     = (const float*)d_in[6];
    /* b2 (d_in[7]) cancels in softmax */
    const float* Wiz    = (const float*)d_in[8];
    const float* biz    = (const float*)d_in[9];
    const float* Wir    = (const float*)d_in[10];
    const float* bir    = (const float*)d_in[11];
    const float* Wih    = (const float*)d_in[12];
    const float* bih    = (const float*)d_in[13];
    const float* Whz    = (const float*)d_in[14];
    const float* bhz    = (const float*)d_in[15];
    const float* Whr    = (const float*)d_in[16];
    const float* bhr    = (const float*)d_in[17];
    const float* Whh    = (const float*)d_in[18];
    const float* bhh    = (const float*)d_in[19];
    const float* Wout   = (const float*)d_in[20];
    const float* bout   = (const float*)d_in[21];

    float* out = (float*)d_out;
    float* att = out + (size_t)BB * TT * VV;

    static int attr_set = 0;
    if (!attr_set) {
        cudaFuncSetAttribute(recurrence_kernel,
                             cudaFuncAttributeMaxDynamicSharedMemorySize, REC_DSMEM);
        attr_set = 1;
    }

    prep_kernel<<<256, 256>>>(W1, Wiz, Wir, Wih, Whz, bhz, Whr, bhr, Whh, bhh);
    combo_kernel<<<4896, 128>>>(ann, emb, inputs, Wout, b1, biz, bir, bih);
    recurrence_kernel<<<128, 256, REC_DSMEM>>>(hinit, W2, att);
    gemm_mma_kernel<<<dim3(16, 250), 256>>>(bout, out);
}

// round 8
// speedup vs baseline: 1.3150x; 1.0277x over previous
#include <cuda_runtime.h>
#include <cuda_fp16.h>
#include <cstdint>

// Problem constants
#define BB   32
#define TT   64
#define SS   64
#define HH   256
#define VV   32000

// ---------------------------------------------------------------------------
// PTX helpers
// ---------------------------------------------------------------------------
__device__ __forceinline__ uint32_t smem_u32(const void* p) {
    uint32_t a;
    asm("{ .reg .u64 t; cvta.to.shared.u64 t, %1; cvt.u32.u64 %0, t; }" : "=r"(a) : "l"(p));
    return a;
}
__device__ __forceinline__ void cp_async16(uint32_t dst, const void* src) {
    asm volatile("cp.async.cg.shared.global [%0], [%1], 16;" :: "r"(dst), "l"(src));
}
#define CP_COMMIT() asm volatile("cp.async.commit_group;" ::: "memory")
#define CP_WAIT(n)  asm volatile("cp.async.wait_group %0;" :: "n"(n) : "memory")

__device__ __forceinline__ void ldsm_x4(uint32_t addr, uint32_t& r0, uint32_t& r1,
                                        uint32_t& r2, uint32_t& r3) {
    asm volatile("ldmatrix.sync.aligned.m8n8.x4.shared.b16 {%0,%1,%2,%3}, [%4];"
                 : "=r"(r0), "=r"(r1), "=r"(r2), "=r"(r3) : "r"(addr));
}
__device__ __forceinline__ void mma16816(float* c, const uint32_t* a,
                                         uint32_t b0, uint32_t b1) {
    asm volatile("mma.sync.aligned.m16n8k16.row.col.f32.f16.f16.f32 "
                 "{%0,%1,%2,%3}, {%4,%5,%6,%7}, {%8,%9}, {%0,%1,%2,%3};"
                 : "+f"(c[0]), "+f"(c[1]), "+f"(c[2]), "+f"(c[3])
                 : "r"(a[0]), "r"(a[1]), "r"(a[2]), "r"(a[3]), "r"(b0), "r"(b1));
}
__device__ __forceinline__ uint32_t ctarank() {
    uint32_t r; asm("mov.u32 %0, %%cluster_ctarank;" : "=r"(r)); return r;
}
__device__ __forceinline__ uint32_t mapa_u32(uint32_t laddr, uint32_t rank) {
    uint32_t r;
    asm("mapa.shared::cluster.u32 %0, %1, %2;" : "=r"(r) : "r"(laddr), "r"(rank));
    return r;
}
__device__ __forceinline__ void st_cluster_f32(uint32_t addr, float v) {
    asm volatile("st.shared::cluster.f32 [%0], %1;" :: "r"(addr), "f"(v) : "memory");
}
#define CLUSTER_SYNC() do { \
    asm volatile("barrier.cluster.arrive.aligned;" ::: "memory"); \
    asm volatile("barrier.cluster.wait.aligned;" ::: "memory"); \
} while (0)

// ---------------------------------------------------------------------------
// Device scratch
// ---------------------------------------------------------------------------
__device__ __align__(16) float g_Wcat[256 * 1024];     // [k][qproj|Whz|Whr|Whh]
__device__ __align__(16) float g_bcat[1024];
__device__ __align__(16) float g_Wann[256 * 1024];
__device__ __align__(16) float g_Wx[256 * 768];
__device__ __align__(16) float g_annprojB[2048 * 256]; // [(b*S+s)][256]  (+b1)
__device__ __align__(16) float g_annWi[2048 * 768];    // [(b*S+s)][768]
__device__ __align__(16) float g_xproj[2048 * 768];    // [(t*B+b)][768]  (+bi*)
__device__ __align__(16) __half g_Ah[2048 * 512];      // [A_hi(256)|A_lo(256)]
__device__ __align__(16) __half g_Bh[32000L * 256];    // B_hi, K-major

// ---------------------------------------------------------------------------
// K0: build fused weight matrices
// ---------------------------------------------------------------------------
__global__ void prep_kernel(const float* __restrict__ W1,
                            const float* __restrict__ Wiz, const float* __restrict__ Wir,
                            const float* __restrict__ Wih,
                            const float* __restrict__ Whz, const float* __restrict__ bhz,
                            const float* __restrict__ Whr, const float* __restrict__ bhr,
                            const float* __restrict__ Whh, const float* __restrict__ bhh) {
    int idx = blockIdx.x * blockDim.x + threadIdx.x;
    int stride = gridDim.x * blockDim.x;
    for (int i = idx; i < 256 * 1024; i += stride) {
        int k = i >> 10, j = i & 1023;
        float wc, wa;
        if (j < 256)      { wc = W1[k * 256 + j];          wa = W1[(256 + k) * 256 + j]; }
        else if (j < 512) { wc = Whz[k * 256 + j - 256];   wa = Wiz[k * 256 + j - 256]; }
        else if (j < 768) { wc = Whr[k * 256 + j - 512];   wa = Wir[k * 256 + j - 512]; }
        else              { wc = Whh[k * 256 + j - 768];   wa = Wih[k * 256 + j - 768]; }
        g_Wcat[i] = wc; g_Wann[i] = wa;
    }
    for (int i = idx; i < 256 * 768; i += stride) {
        int k = i / 768, j = i % 768;
        float w;
        if (j < 256)      w = Wiz[(256 + k) * 256 + j];
        else if (j < 512) w = Wir[(256 + k) * 256 + j - 256];
        else              w = Wih[(256 + k) * 256 + j - 512];
        g_Wx[i] = w;
    }
    for (int i = idx; i < 1024; i += stride) {
        float bv = 0.f;
        if (i >= 256 && i < 512)      bv = bhz[i - 256];
        else if (i >= 512 && i < 768) bv = bhr[i - 512];
        else if (i >= 768)            bv = bhh[i - 768];
        g_bcat[i] = bv;
    }
}

// ---------------------------------------------------------------------------
// K1 combo: sgemm mode1 (512 CTAs) + sgemm mode2 (384) + Wout->fp16 (4000)
// ---------------------------------------------------------------------------
__global__ void __launch_bounds__(128)
combo_kernel(const float* __restrict__ ann, const float* __restrict__ emb,
             const int* __restrict__ inputs, const float* __restrict__ Wout,
             const float* __restrict__ b1, const float* __restrict__ biz,
             const float* __restrict__ bir, const float* __restrict__ bih) {
    __shared__ __align__(16) float sm[2][64 * 20 + 16 * 68];
    __shared__ __align__(16) float sw[32 * 68];
    __shared__ int tok[64];

    const int bid = blockIdx.x, tid = threadIdx.x;

    if (bid >= 896) {
        int b3 = bid - 896;
        int k0 = (b3 & 7) * 32, n0 = (b3 >> 3) * 64;
        for (int i = tid; i < 32 * 64; i += 128) {
            int k = i >> 6, n = i & 63;
            sw[k * 68 + n] = Wout[(size_t)(k0 + k) * VV + n0 + n];
        }
        __syncthreads();
        const int n = tid >> 1, kh = (tid & 1) * 16;
        __align__(16) __half vals[16];
#pragma unroll
        for (int j = 0; j < 16; j++) vals[j] = __float2half(sw[(kh + j) * 68 + n]);
        __half* dst = g_Bh + (size_t)(n0 + n) * 256 + k0 + kh;
        *(uint4*)dst       = ((const uint4*)vals)[0];
        *(uint4*)(dst + 8) = ((const uint4*)vals)[1];
        return;
    }

    const bool m1 = bid < 512;
    int row0, col0, N;
    const float* Bm;
    if (m1) { row0 = (bid >> 4) * 64; col0 = (bid & 15) * 64; N = 1024; Bm = g_Wann; }
    else    { int b2 = bid - 512; row0 = (b2 / 12) * 64; col0 = (b2 % 12) * 64; N = 768; Bm = g_Wx; }

    if (!m1 && tid < 64) {
        int r = row0 + tid;
        tok[tid] = inputs[(r & 31) * TT + (r >> 5)];
    }
    if (!m1) __syncthreads();

    const int rA = tid >> 2, kqA = (tid & 3) * 4;
    const int kB = tid >> 4, nB = (tid & 15) * 4;
    const float* ArowA = m1 ? (ann + (size_t)(row0 + rA) * 256)
                            : (emb + (size_t)tok[rA] * 256);
    const float* ArowB = m1 ? (ann + (size_t)(row0 + rA + 32) * 256)
                            : (emb + (size_t)tok[rA + 32] * 256);
    const float* Bcol = Bm + col0;

    {
        float4 a0 = *(const float4*)(ArowA + kqA);
        float4 a1 = *(const float4*)(ArowB + kqA);
        float4 b0 = *(const float4*)(Bcol + (size_t)kB * N + nB);
        float4 b1v = *(const float4*)(Bcol + (size_t)(kB + 8) * N + nB);
        *(float4*)&sm[0][rA * 20 + kqA]        = a0;
        *(float4*)&sm[0][(rA + 32) * 20 + kqA] = a1;
        *(float4*)&sm[0][1280 + kB * 68 + nB]        = b0;
        *(float4*)&sm[0][1280 + (kB + 8) * 68 + nB]  = b1v;
    }
    __syncthreads();

    float acc[4][8];
#pragma unroll
    for (int i = 0; i < 4; i++)
#pragma unroll
        for (int j = 0; j < 8; j++) acc[i][j] = 0.f;

    const int ty4 = (tid >> 3) * 4, tx8 = (tid & 7) * 8;
    int buf = 0;

#pragma unroll 1
    for (int kt = 0; kt < 16; kt++) {
        float4 nA0, nA1, nB0, nB1;
        if (kt < 15) {
            int k0 = (kt + 1) * 16;
            nA0 = *(const float4*)(ArowA + k0 + kqA);
            nA1 = *(const float4*)(ArowB + k0 + kqA);
            nB0 = *(const float4*)(Bcol + (size_t)(k0 + kB) * N + nB);
            nB1 = *(const float4*)(Bcol + (size_t)(k0 + kB + 8) * N + nB);
        }
        const float* As_ = &sm[buf][0];
        const float* Bs_ = &sm[buf][1280];
#pragma unroll
        for (int kk = 0; kk < 16; kk++) {
            float a[4], b[8];
#pragma unroll
            for (int i = 0; i < 4; i++) a[i] = As_[(ty4 + i) * 20 + kk];
            *(float4*)&b[0] = *(const float4*)&Bs_[kk * 68 + tx8];
            *(float4*)&b[4] = *(const float4*)&Bs_[kk * 68 + tx8 + 4];
#pragma unroll
            for (int i = 0; i < 4; i++)
#pragma unroll
                for (int j = 0; j < 8; j++) acc[i][j] += a[i] * b[j];
        }
        if (kt < 15) {
            buf ^= 1;
            __syncthreads();
            *(float4*)&sm[buf][rA * 20 + kqA]        = nA0;
            *(float4*)&sm[buf][(rA + 32) * 20 + kqA] = nA1;
            *(float4*)&sm[buf][1280 + kB * 68 + nB]        = nB0;
            *(float4*)&sm[buf][1280 + (kB + 8) * 68 + nB]  = nB1;
            __syncthreads();
        }
    }

#pragma unroll
    for (int i = 0; i < 4; i++) {
        int r = row0 + ty4 + i;
#pragma unroll
        for (int j = 0; j < 8; j++) {
            int cidx = col0 + tx8 + j;
            float v = acc[i][j];
            if (m1) {
                if (cidx < 256) g_annprojB[(size_t)r * 256 + cidx] = v + b1[cidx];
                else            g_annWi[(size_t)r * 768 + (cidx - 256)] = v;
            } else {
                float bv = (cidx < 256) ? biz[cidx]
                         : (cidx < 512) ? bir[cidx - 256] : bih[cidx - 512];
                g_xproj[(size_t)r * 768 + cidx] = v + bv;
            }
        }
    }
}

// ---------------------------------------------------------------------------
// K3: clustered recurrence, conflict-free SMEM layouts.
// 16 clusters x 8 CTAs x 2 batches; rank q owns 32 cols of each gate block.
// ---------------------------------------------------------------------------
// dsm float offsets
#define O_WS   0        // [k 0..255][j 0..127]  weights, j contiguous
#define O_QT   32768    // [bb][c 0..31][s 0..63] annproj transposed
#define O_TILE 36864    // [bb][s 0..63][c 0..95] annWi (z|r|h) pitch 96
#define O_HS   49152    // 2 x 256 hidden state
#define O_HC   49664    // 2 x 128 hcat slice
#define O_PA   49920    // 2 x 128 phase-A k-half partials
#define O_UPA  50176    // 8 x 128 logit partials (all-gathered)
#define O_AL   51200    // 2 x 64 alpha
#define O_ZR   51328    // 2 x 64 (z | r)
#define O_PHB  51456    // 2 x 32 hbar pre
#define O_XPS  51520    // 2 x 96 xproj slice (cp.async)
#define O_BS   51712    // 128 bias
#define O_W2   51840    // 32
#define REC_NF 51872
#define REC_DSMEM (REC_NF * 4)

__global__ void __launch_bounds__(256, 1) __cluster_dims__(8, 1, 1)
recurrence_kernel(const float* __restrict__ hidden_init,
                  const float* __restrict__ W2,
                  float* __restrict__ att_out) {
    extern __shared__ __align__(16) float dsm[];
    __shared__ float red_m[4], red_s[4];

    const int tid = threadIdx.x;
    const uint32_t q = ctarank();
    const int b0 = (blockIdx.x >> 3) * 2;
    const uint32_t sbase = smem_u32(dsm);

    // ---- init ----
    for (int i = tid; i < 256 * 128; i += 256) {
        int k = i >> 7, j = i & 127;
        int gcol = (j >> 5) * 256 + (int)q * 32 + (j & 31);
        dsm[O_WS + k * 128 + j] = g_Wcat[k * 1024 + gcol];
    }
    for (int i = tid; i < 2 * 32 * 64; i += 256) {
        int bb = i >> 11, c = (i >> 6) & 31, s = i & 63;
        dsm[O_QT + i] = g_annprojB[(size_t)((b0 + bb) * 64 + s) * 256 + q * 32 + c];
    }
    for (int i = tid; i < 2 * 64 * 96; i += 256) {
        int bb = i / 6144, rem = i % 6144;
        int s = rem / 96, c = rem % 96;
        dsm[O_TILE + i] = g_annWi[(size_t)((b0 + bb) * 64 + s) * 768
                                  + (c >> 5) * 256 + q * 32 + (c & 31)];
    }
    if (tid < 128) {
        int gcol = (tid >> 5) * 256 + (int)q * 32 + (tid & 31);
        dsm[O_BS + tid] = g_bcat[gcol];
    }
    if (tid < 32) dsm[O_W2 + tid] = W2[q * 32 + tid];
    for (int i = tid; i < 512; i += 256)
        dsm[O_HS + i] = hidden_init[(b0 + (i >> 8)) * 256 + (i & 255)];
    __syncthreads();
    CLUSTER_SYNC();

#pragma unroll 1
    for (int t = 0; t < TT; t++) {
        // ---- (0) xproj prefetch by threads 128..175 ----
        if (tid >= 128 && tid < 176) {
            int idx = tid - 128;                   // 0..47
            int bb = idx / 24, rem = idx % 24;
            int g = rem >> 3, c8 = rem & 7;
            const float* src = g_xproj + (size_t)(t * 32 + b0 + bb) * 768
                             + g * 256 + q * 32 + c8 * 4;
            cp_async16(sbase + (O_XPS + bb * 96 + g * 32 + c8 * 4) * 4, src);
            CP_COMMIT();
        }

        // ---- (1) phase A: hcat, k split 2 ways over 256 threads ----
        {
            const int j = tid & 127;
            const int kh = (tid >> 7) * 128;
            const float* wp = &dsm[O_WS + kh * 128 + j];
            const float* h0 = &dsm[O_HS + kh];
            const float* h1 = &dsm[O_HS + 256 + kh];
            float a0 = 0.f, a1 = 0.f;
#pragma unroll 8
            for (int k = 0; k < 128; k += 4) {
                float4 hv0 = *(const float4*)(h0 + k);
                float4 hv1 = *(const float4*)(h1 + k);
                float w0 = wp[k * 128], w1 = wp[(k + 1) * 128];
                float w2v = wp[(k + 2) * 128], w3 = wp[(k + 3) * 128];
                a0 += hv0.x * w0 + hv0.y * w1 + hv0.z * w2v + hv0.w * w3;
                a1 += hv1.x * w0 + hv1.y * w1 + hv1.z * w2v + hv1.w * w3;
            }
            if (tid >= 128) { dsm[O_PA + j] = a0; dsm[O_PA + 128 + j] = a1; }
            __syncthreads();
            if (tid < 128) {
                float b = dsm[O_BS + tid];
                dsm[O_HC + tid]       = a0 + dsm[O_PA + tid] + b;
                dsm[O_HC + 128 + tid] = a1 + dsm[O_PA + 128 + tid] + b;
            }
            __syncthreads();
        }

        // ---- (2) logits: 128 threads, transposed qproj tile (conflict-free) ----
        if (tid < 128) {
            const int bb = tid >> 6, s = tid & 63;
            const float* qt = &dsm[O_QT + bb * 2048 + s];
            const float* hq = &dsm[O_HC + bb * 128];
            const float* w2 = &dsm[O_W2];
            float u0 = 0.f, u1 = 0.f;
#pragma unroll
            for (int c = 0; c < 32; c += 4) {
                float4 hv = *(const float4*)(hq + c);
                float4 wv = *(const float4*)(w2 + c);
                u0 += wv.x * fmaxf(hv.x + qt[c * 64], 0.f)
                    + wv.y * fmaxf(hv.y + qt[(c + 1) * 64], 0.f);
                u1 += wv.z * fmaxf(hv.z + qt[(c + 2) * 64], 0.f)
                    + wv.w * fmaxf(hv.w + qt[(c + 3) * 64], 0.f);
            }
            float u = u0 + u1;
            uint32_t la = sbase + (O_UPA + (int)q * 128 + tid) * 4;
#pragma unroll
            for (int rk = 0; rk < 8; rk++)
                st_cluster_f32(mapa_u32(la, rk), u);
        }
        CLUSTER_SYNC();  // sync1: all logit partials delivered everywhere

        // ---- (3) softmax (redundant per rank) ----
        float u_v = 0.f, e_v = 0.f;
        if (tid < 128) {
#pragma unroll
            for (int r = 0; r < 8; r++) u_v += dsm[O_UPA + r * 128 + tid];
            float m = u_v;
#pragma unroll
            for (int o = 16; o; o >>= 1) m = fmaxf(m, __shfl_xor_sync(0xffffffffu, m, o));
            if ((tid & 31) == 0) red_m[tid >> 5] = m;
        }
        __syncthreads();
        if (tid < 128) {
            int bb = tid >> 6;
            float m = fmaxf(red_m[bb * 2], red_m[bb * 2 + 1]);
            e_v = __expf(u_v - m);
            float sum = e_v;
#pragma unroll
            for (int o = 16; o; o >>= 1) sum += __shfl_xor_sync(0xffffffffu, sum, o);
            if ((tid & 31) == 0) red_s[tid >> 5] = sum;
        }
        __syncthreads();
        if (tid < 128) {
            int bb = tid >> 6, s = tid & 63;
            float inv = 1.f / (red_s[bb * 2] + red_s[bb * 2 + 1]);
            float al = e_v * inv;
            dsm[O_AL + tid] = al;
            if (q == 0) att_out[((b0 + bb) * SS + s) * TT + t] = al;
        }
        CP_WAIT(0);
        __syncthreads();

        // ---- (4) gate sums + activations (all local, pitch-96 coalesced) ----
        if (tid < 192) {
            int bb = tid >= 96;
            int cc = tid - bb * 96;                // 0..95 within annWi slice
            const float* tp = &dsm[O_TILE + bb * 6144 + cc];
            const float* ap = &dsm[O_AL + bb * 64];
            float acc0 = 0.f, acc1 = 0.f;
#pragma unroll 8
            for (int s = 0; s < 64; s += 2) {
                acc0 += ap[s] * tp[s * 96];
                acc1 += ap[s + 1] * tp[(s + 1) * 96];
            }
            float pre = acc0 + acc1 + dsm[O_XPS + bb * 96 + cc];
            if (cc < 64) {
                float v = 1.f / (1.f + __expf(-(pre + dsm[O_HC + bb * 128 + 32 + cc])));
                dsm[O_ZR + bb * 64 + cc] = v;
            } else {
                dsm[O_PHB + bb * 32 + cc - 64] = pre;
            }
        }
        __syncthreads();

        // ---- (5) GRU combine (local dims) + h broadcast ----
        if (tid < 64) {
            int bb = tid >> 5, jj = tid & 31;
            int dg = (int)q * 32 + jj;
            float z = dsm[O_ZR + bb * 64 + jj];
            float r = dsm[O_ZR + bb * 64 + 32 + jj];
            float g = tanhf(dsm[O_PHB + bb * 32 + jj] + r * dsm[O_HC + bb * 128 + 96 + jj]);
            float hold = dsm[O_HS + bb * 256 + dg];
            float hn = (1.f - z) * g + z * hold;
            uint32_t la = sbase + (O_HS + bb * 256 + dg) * 4;
#pragma unroll
            for (int rk = 0; rk < 8; rk++)
                st_cluster_f32(mapa_u32(la, rk), hn);
            __half hi = __float2half(hn);
            __half lo = __float2half(hn - __half2float(hi));
            size_t rb = (size_t)((b0 + bb) * 64 + t) * 512;
            g_Ah[rb + dg]       = hi;
            g_Ah[rb + 256 + dg] = lo;
        }
        CLUSTER_SYNC();  // sync2: new h visible everywhere
    }
}

// ---------------------------------------------------------------------------
// K4: HMMA fp16 GEMM (unchanged - 207us, tensor 53%)
// ---------------------------------------------------------------------------
#define GSTAGES 3

__global__ void __launch_bounds__(256, 2)
gemm_mma_kernel(const float* __restrict__ bout, float* __restrict__ out) {
    __shared__ __align__(128) __half sA[GSTAGES][128 * 32];
    __shared__ __align__(128) __half sB[GSTAGES][128 * 32];

    const int tid  = threadIdx.x;
    const int lane = tid & 31, wid = tid >> 5;
    const int wr = wid >> 2, wc = wid & 3;
    const int row0 = blockIdx.x * 128, col0 = blockIdx.y * 128;

    const __half* Ag = g_Ah + (size_t)row0 * 512;
    const __half* Bg = g_Bh + (size_t)col0 * 256;

    const uint32_t sAb = smem_u32(sA);
    const uint32_t sBb = smem_u32(sB);

    const int rA0 = tid >> 2,          cA0 = tid & 3;
    const int rA1 = (tid + 256) >> 2;
    const uint32_t dA0 = rA0 * 64 + ((cA0 ^ ((rA0 >> 1) & 3)) * 16);
    const uint32_t dA1 = rA1 * 64 + ((cA0 ^ ((rA1 >> 1) & 3)) * 16);

#define LOAD_STAGE(s, kt) do {                                                       \
        uint32_t ab = sAb + (s) * 8192, bb = sBb + (s) * 8192;                       \
        int bk = ((kt) & 7) * 32;                                                    \
        cp_async16(ab + dA0, Ag + (size_t)rA0 * 512 + (kt) * 32 + cA0 * 8);          \
        cp_async16(ab + dA1, Ag + (size_t)rA1 * 512 + (kt) * 32 + cA0 * 8);          \
        cp_async16(bb + dA0, Bg + (size_t)rA0 * 256 + bk + cA0 * 8);                 \
        cp_async16(bb + dA1, Bg + (size_t)rA1 * 256 + bk + cA0 * 8);                 \
    } while (0)

    LOAD_STAGE(0, 0); CP_COMMIT();
    LOAD_STAGE(1, 1); CP_COMMIT();

    float acc[4][4][4];
#pragma unroll
    for (int i = 0; i < 4; i++)
#pragma unroll
        for (int j = 0; j < 4; j++)
#pragma unroll
            for (int qq = 0; qq < 4; qq++) acc[i][j][qq] = 0.f;

    const int aRow = lane & 15;
    const int aSel = lane >> 4;
    const int bRow = (lane & 7) + ((lane >> 4) << 3);
    const int bSel = (lane >> 3) & 1;

#pragma unroll 1
    for (int kt = 0; kt < 16; kt++) {
        CP_WAIT(1);
        __syncthreads();
        if (kt + 2 < 16) LOAD_STAGE((kt + 2) % GSTAGES, kt + 2);
        CP_COMMIT();

        const int st = kt % GSTAGES;
        const uint32_t ab = sAb + st * 8192;
        const uint32_t bb = sBb + st * 8192;

#pragma unroll
        for (int kf = 0; kf < 2; kf++) {
            uint32_t aF[4][4];
#pragma unroll
            for (int mf = 0; mf < 4; mf++) {
                int row = wr * 64 + mf * 16 + aRow;
                int ch  = (kf * 2 + aSel) ^ ((row >> 1) & 3);
                ldsm_x4(ab + row * 64 + ch * 16, aF[mf][0], aF[mf][1], aF[mf][2], aF[mf][3]);
            }
            uint32_t bF[2][4];
#pragma unroll
            for (int nf2 = 0; nf2 < 2; nf2++) {
                int row = wc * 32 + nf2 * 16 + bRow;
                int ch  = (kf * 2 + bSel) ^ ((row >> 1) & 3);
                ldsm_x4(bb + row * 64 + ch * 16, bF[nf2][0], bF[nf2][1], bF[nf2][2], bF[nf2][3]);
            }
#pragma unroll
            for (int mf = 0; mf < 4; mf++)
#pragma unroll
                for (int nf = 0; nf < 4; nf++) {
                    uint32_t b0 = bF[nf >> 1][(nf & 1) * 2 + 0];
                    uint32_t b1 = bF[nf >> 1][(nf & 1) * 2 + 1];
                    mma16816(acc[mf][nf], aF[mf], b0, b1);
                }
        }
        __syncthreads();
    }

    const int rq = lane >> 2, cq = (lane & 3) * 2;
    const int rbase = row0 + wr * 64, cbase = col0 + wc * 32;
#pragma unroll
    for (int mf = 0; mf < 4; mf++) {
#pragma unroll
        for (int nf = 0; nf < 4; nf++) {
            int r  = rbase + mf * 16 + rq;
            int cc = cbase + nf * 8 + cq;
            float bz0 = bout[cc], bz1 = bout[cc + 1];
            float2 v0 = make_float2(acc[mf][nf][0] + bz0, acc[mf][nf][1] + bz1);
            float2 v1 = make_float2(acc[mf][nf][2] + bz0, acc[mf][nf][3] + bz1);
            *(float2*)&out[(size_t)r * VV + cc]       = v0;
            *(float2*)&out[(size_t)(r + 8) * VV + cc] = v1;
        }
    }
#undef LOAD_STAGE
}

// ---------------------------------------------------------------------------
extern "C" void kernel_launch(void* const* d_in, const int* in_sizes, int n_in,
                              void* d_out, int out_size) {
    const int*   inputs = (const int*)  d_in[0];
    const float* ann    = (const float*)d_in[1];
    const float* hinit  = (const float*)d_in[2];
    const float* emb    = (const float*)d_in[3];
    const float* W1     = (const float*)d_in[4];
    const float* b1     = (const float*)d_in[5];
    const float* W2     = (const float*)d_in[6];
    /* b2 (d_in[7]) cancels in softmax */
    const float* Wiz    = (const float*)d_in[8];
    const float* biz    = (const float*)d_in[9];
    const float* Wir    = (const float*)d_in[10];
    const float* bir    = (const float*)d_in[11];
    const float* Wih    = (const float*)d_in[12];
    const float* bih    = (const float*)d_in[13];
    const float* Whz    = (const float*)d_in[14];
    const float* bhz    = (const float*)d_in[15];
    const float* Whr    = (const float*)d_in[16];
    const float* bhr    = (const float*)d_in[17];
    const float* Whh    = (const float*)d_in[18];
    const float* bhh    = (const float*)d_in[19];
    const float* Wout   = (const float*)d_in[20];
    const float* bout   = (const float*)d_in[21];

    float* out = (float*)d_out;
    float* att = out + (size_t)BB * TT * VV;

    static int attr_set = 0;
    if (!attr_set) {
        cudaFuncSetAttribute(recurrence_kernel,
                             cudaFuncAttributeMaxDynamicSharedMemorySize, REC_DSMEM);
        attr_set = 1;
    }

    prep_kernel<<<256, 256>>>(W1, Wiz, Wir, Wih, Whz, bhz, Whr, bhr, Whh, bhh);
    combo_kernel<<<4896, 128>>>(ann, emb, inputs, Wout, b1, biz, bir, bih);
    recurrence_kernel<<<128, 256, REC_DSMEM>>>(hinit, W2, att);
    gemm_mma_kernel<<<dim3(16, 250), 256>>>(bout, out);
}

// round 9
// speedup vs baseline: 1.3302x; 1.0116x over previous
#include <cuda_runtime.h>
#include <cuda_fp16.h>
#include <cstdint>

// Problem constants
#define BB   32
#define TT   64
#define SS   64
#define HH   256
#define VV   32000

// ---------------------------------------------------------------------------
// PTX helpers
// ---------------------------------------------------------------------------
__device__ __forceinline__ uint32_t smem_u32(const void* p) {
    uint32_t a;
    asm("{ .reg .u64 t; cvta.to.shared.u64 t, %1; cvt.u32.u64 %0, t; }" : "=r"(a) : "l"(p));
    return a;
}
__device__ __forceinline__ void cp_async16(uint32_t dst, const void* src) {
    asm volatile("cp.async.cg.shared.global [%0], [%1], 16;" :: "r"(dst), "l"(src));
}
#define CP_COMMIT() asm volatile("cp.async.commit_group;" ::: "memory")
#define CP_WAIT(n)  asm volatile("cp.async.wait_group %0;" :: "n"(n) : "memory")

__device__ __forceinline__ void ldsm_x4(uint32_t addr, uint32_t& r0, uint32_t& r1,
                                        uint32_t& r2, uint32_t& r3) {
    asm volatile("ldmatrix.sync.aligned.m8n8.x4.shared.b16 {%0,%1,%2,%3}, [%4];"
                 : "=r"(r0), "=r"(r1), "=r"(r2), "=r"(r3) : "r"(addr));
}
__device__ __forceinline__ void mma16816(float* c, const uint32_t* a,
                                         uint32_t b0, uint32_t b1) {
    asm volatile("mma.sync.aligned.m16n8k16.row.col.f32.f16.f16.f32 "
                 "{%0,%1,%2,%3}, {%4,%5,%6,%7}, {%8,%9}, {%0,%1,%2,%3};"
                 : "+f"(c[0]), "+f"(c[1]), "+f"(c[2]), "+f"(c[3])
                 : "r"(a[0]), "r"(a[1]), "r"(a[2]), "r"(a[3]), "r"(b0), "r"(b1));
}
__device__ __forceinline__ uint32_t ctarank() {
    uint32_t r; asm("mov.u32 %0, %%cluster_ctarank;" : "=r"(r)); return r;
}
__device__ __forceinline__ uint32_t mapa_u32(uint32_t laddr, uint32_t rank) {
    uint32_t r;
    asm("mapa.shared::cluster.u32 %0, %1, %2;" : "=r"(r) : "r"(laddr), "r"(rank));
    return r;
}
__device__ __forceinline__ void st_cluster_f32(uint32_t addr, float v) {
    asm volatile("st.shared::cluster.f32 [%0], %1;" :: "r"(addr), "f"(v) : "memory");
}
#define CLUSTER_SYNC() do { \
    asm volatile("barrier.cluster.arrive.aligned;" ::: "memory"); \
    asm volatile("barrier.cluster.wait.aligned;" ::: "memory"); \
} while (0)

// ---------------------------------------------------------------------------
// Device scratch
// ---------------------------------------------------------------------------
__device__ __align__(16) float g_Wcat[256 * 1024];     // [k][qproj|Whz|Whr|Whh]
__device__ __align__(16) float g_bcat[1024];
__device__ __align__(16) float g_Wann[256 * 1024];
__device__ __align__(16) float g_Wx[256 * 768];
__device__ __align__(16) float g_annprojB[2048 * 256]; // [(b*S+s)][256]  (+b1)
__device__ __align__(16) float g_annWi[2048 * 768];    // [(b*S+s)][768]
__device__ __align__(16) float g_xproj[2048 * 768];    // [(t*B+b)][768]  (+bi*)
__device__ __align__(16) __half g_Ah[2048 * 512];      // [A_hi(256)|A_lo(256)]
__device__ __align__(16) __half g_Bh[32000L * 256];    // B_hi, K-major

// ---------------------------------------------------------------------------
// K0: build fused weight matrices
// ---------------------------------------------------------------------------
__global__ void prep_kernel(const float* __restrict__ W1,
                            const float* __restrict__ Wiz, const float* __restrict__ Wir,
                            const float* __restrict__ Wih,
                            const float* __restrict__ Whz, const float* __restrict__ bhz,
                            const float* __restrict__ Whr, const float* __restrict__ bhr,
                            const float* __restrict__ Whh, const float* __restrict__ bhh) {
    int idx = blockIdx.x * blockDim.x + threadIdx.x;
    int stride = gridDim.x * blockDim.x;
    for (int i = idx; i < 256 * 1024; i += stride) {
        int k = i >> 10, j = i & 1023;
        float wc, wa;
        if (j < 256)      { wc = W1[k * 256 + j];          wa = W1[(256 + k) * 256 + j]; }
        else if (j < 512) { wc = Whz[k * 256 + j - 256];   wa = Wiz[k * 256 + j - 256]; }
        else if (j < 768) { wc = Whr[k * 256 + j - 512];   wa = Wir[k * 256 + j - 512]; }
        else              { wc = Whh[k * 256 + j - 768];   wa = Wih[k * 256 + j - 768]; }
        g_Wcat[i] = wc; g_Wann[i] = wa;
    }
    for (int i = idx; i < 256 * 768; i += stride) {
        int k = i / 768, j = i % 768;
        float w;
        if (j < 256)      w = Wiz[(256 + k) * 256 + j];
        else if (j < 512) w = Wir[(256 + k) * 256 + j - 256];
        else              w = Wih[(256 + k) * 256 + j - 512];
        g_Wx[i] = w;
    }
    for (int i = idx; i < 1024; i += stride) {
        float bv = 0.f;
        if (i >= 256 && i < 512)      bv = bhz[i - 256];
        else if (i >= 512 && i < 768) bv = bhr[i - 512];
        else if (i >= 768)            bv = bhh[i - 768];
        g_bcat[i] = bv;
    }
}

// ---------------------------------------------------------------------------
// K1 combo: sgemm mode1 (512 CTAs) + sgemm mode2 (384) + Wout->fp16 (4000)
// ---------------------------------------------------------------------------
__global__ void __launch_bounds__(128)
combo_kernel(const float* __restrict__ ann, const float* __restrict__ emb,
             const int* __restrict__ inputs, const float* __restrict__ Wout,
             const float* __restrict__ b1, const float* __restrict__ biz,
             const float* __restrict__ bir, const float* __restrict__ bih) {
    __shared__ __align__(16) float sm[2][64 * 20 + 16 * 68];
    __shared__ __align__(16) float sw[32 * 68];
    __shared__ int tok[64];

    const int bid = blockIdx.x, tid = threadIdx.x;

    if (bid >= 896) {
        int b3 = bid - 896;
        int k0 = (b3 & 7) * 32, n0 = (b3 >> 3) * 64;
        for (int i = tid; i < 32 * 64; i += 128) {
            int k = i >> 6, n = i & 63;
            sw[k * 68 + n] = Wout[(size_t)(k0 + k) * VV + n0 + n];
        }
        __syncthreads();
        const int n = tid >> 1, kh = (tid & 1) * 16;
        __align__(16) __half vals[16];
#pragma unroll
        for (int j = 0; j < 16; j++) vals[j] = __float2half(sw[(kh + j) * 68 + n]);
        __half* dst = g_Bh + (size_t)(n0 + n) * 256 + k0 + kh;
        *(uint4*)dst       = ((const uint4*)vals)[0];
        *(uint4*)(dst + 8) = ((const uint4*)vals)[1];
        return;
    }

    const bool m1 = bid < 512;
    int row0, col0, N;
    const float* Bm;
    if (m1) { row0 = (bid >> 4) * 64; col0 = (bid & 15) * 64; N = 1024; Bm = g_Wann; }
    else    { int b2 = bid - 512; row0 = (b2 / 12) * 64; col0 = (b2 % 12) * 64; N = 768; Bm = g_Wx; }

    if (!m1 && tid < 64) {
        int r = row0 + tid;
        tok[tid] = inputs[(r & 31) * TT + (r >> 5)];
    }
    if (!m1) __syncthreads();

    const int rA = tid >> 2, kqA = (tid & 3) * 4;
    const int kB = tid >> 4, nB = (tid & 15) * 4;
    const float* ArowA = m1 ? (ann + (size_t)(row0 + rA) * 256)
                            : (emb + (size_t)tok[rA] * 256);
    const float* ArowB = m1 ? (ann + (size_t)(row0 + rA + 32) * 256)
                            : (emb + (size_t)tok[rA + 32] * 256);
    const float* Bcol = Bm + col0;

    {
        float4 a0 = *(const float4*)(ArowA + kqA);
        float4 a1 = *(const float4*)(ArowB + kqA);
        float4 b0 = *(const float4*)(Bcol + (size_t)kB * N + nB);
        float4 b1v = *(const float4*)(Bcol + (size_t)(kB + 8) * N + nB);
        *(float4*)&sm[0][rA * 20 + kqA]        = a0;
        *(float4*)&sm[0][(rA + 32) * 20 + kqA] = a1;
        *(float4*)&sm[0][1280 + kB * 68 + nB]        = b0;
        *(float4*)&sm[0][1280 + (kB + 8) * 68 + nB]  = b1v;
    }
    __syncthreads();

    float acc[4][8];
#pragma unroll
    for (int i = 0; i < 4; i++)
#pragma unroll
        for (int j = 0; j < 8; j++) acc[i][j] = 0.f;

    const int ty4 = (tid >> 3) * 4, tx8 = (tid & 7) * 8;
    int buf = 0;

#pragma unroll 1
    for (int kt = 0; kt < 16; kt++) {
        float4 nA0, nA1, nB0, nB1;
        if (kt < 15) {
            int k0 = (kt + 1) * 16;
            nA0 = *(const float4*)(ArowA + k0 + kqA);
            nA1 = *(const float4*)(ArowB + k0 + kqA);
            nB0 = *(const float4*)(Bcol + (size_t)(k0 + kB) * N + nB);
            nB1 = *(const float4*)(Bcol + (size_t)(k0 + kB + 8) * N + nB);
        }
        const float* As_ = &sm[buf][0];
        const float* Bs_ = &sm[buf][1280];
#pragma unroll
        for (int kk = 0; kk < 16; kk++) {
            float a[4], b[8];
#pragma unroll
            for (int i = 0; i < 4; i++) a[i] = As_[(ty4 + i) * 20 + kk];
            *(float4*)&b[0] = *(const float4*)&Bs_[kk * 68 + tx8];
            *(float4*)&b[4] = *(const float4*)&Bs_[kk * 68 + tx8 + 4];
#pragma unroll
            for (int i = 0; i < 4; i++)
#pragma unroll
                for (int j = 0; j < 8; j++) acc[i][j] += a[i] * b[j];
        }
        if (kt < 15) {
            buf ^= 1;
            __syncthreads();
            *(float4*)&sm[buf][rA * 20 + kqA]        = nA0;
            *(float4*)&sm[buf][(rA + 32) * 20 + kqA] = nA1;
            *(float4*)&sm[buf][1280 + kB * 68 + nB]        = nB0;
            *(float4*)&sm[buf][1280 + (kB + 8) * 68 + nB]  = nB1;
            __syncthreads();
        }
    }

#pragma unroll
    for (int i = 0; i < 4; i++) {
        int r = row0 + ty4 + i;
#pragma unroll
        for (int j = 0; j < 8; j++) {
            int cidx = col0 + tx8 + j;
            float v = acc[i][j];
            if (m1) {
                if (cidx < 256) g_annprojB[(size_t)r * 256 + cidx] = v + b1[cidx];
                else            g_annWi[(size_t)r * 768 + (cidx - 256)] = v;
            } else {
                float bv = (cidx < 256) ? biz[cidx]
                         : (cidx < 512) ? bir[cidx - 256] : bih[cidx - 512];
                g_xproj[(size_t)r * 768 + cidx] = v + bv;
            }
        }
    }
}

// ---------------------------------------------------------------------------
// K3: clustered recurrence v3 — 512 threads/CTA (16 warps) for latency hiding.
// 16 clusters x 8 CTAs x 2 batches; rank q owns 32 cols of each gate block.
// ---------------------------------------------------------------------------
// dsm float offsets
#define O_WS   0        // [k 0..255][j 0..127]  weights, j contiguous
#define O_QT   32768    // [bb][c 0..31][s 0..63] annproj transposed
#define O_TILE 36864    // [bb][s 0..63][c 0..95] annWi (z|r|h) pitch 96
#define O_HS   49152    // 2 x 256 hidden state
#define O_HC   49664    // 2 x 128 hcat slice
#define O_PA   49920    // 4 kq x (2 bb x 128 j) phase-A partials
#define O_UPA  50944    // 8 x 128 logit partials (all-gathered)
#define O_AL   51968    // 2 x 64 alpha
#define O_ZR   52096    // 2 x 64 (z | r)
#define O_PHB  52224    // 2 x 32 hbar pre
#define O_XPS  52288    // 2 x 96 xproj slice (cp.async)
#define O_GP   52480    // 2 halves x 192 gate partials
#define O_BS   52864    // 128 bias
#define O_W2   52992    // 32
#define REC_NF 53024
#define REC_DSMEM (REC_NF * 4)

__global__ void __launch_bounds__(512, 1) __cluster_dims__(8, 1, 1)
recurrence_kernel(const float* __restrict__ hidden_init,
                  const float* __restrict__ W2,
                  float* __restrict__ att_out) {
    extern __shared__ __align__(16) float dsm[];
    __shared__ float red_m[4], red_s[4];

    const int tid = threadIdx.x;
    const uint32_t q = ctarank();
    const int b0 = (blockIdx.x >> 3) * 2;
    const uint32_t sbase = smem_u32(dsm);

    // ---- init ----
    for (int i = tid; i < 256 * 128; i += 512) {
        int k = i >> 7, j = i & 127;
        int gcol = (j >> 5) * 256 + (int)q * 32 + (j & 31);
        dsm[O_WS + k * 128 + j] = g_Wcat[k * 1024 + gcol];
    }
    for (int i = tid; i < 2 * 32 * 64; i += 512) {
        int bb = i >> 11, c = (i >> 6) & 31, s = i & 63;
        dsm[O_QT + i] = g_annprojB[(size_t)((b0 + bb) * 64 + s) * 256 + q * 32 + c];
    }
    for (int i = tid; i < 2 * 64 * 96; i += 512) {
        int bb = i / 6144, rem = i % 6144;
        int s = rem / 96, c = rem % 96;
        dsm[O_TILE + i] = g_annWi[(size_t)((b0 + bb) * 64 + s) * 768
                                  + (c >> 5) * 256 + q * 32 + (c & 31)];
    }
    if (tid < 128) {
        int gcol = (tid >> 5) * 256 + (int)q * 32 + (tid & 31);
        dsm[O_BS + tid] = g_bcat[gcol];
    }
    if (tid >= 128 && tid < 160) dsm[O_W2 + tid - 128] = W2[q * 32 + (tid - 128)];
    if (tid >= 160 && tid < 672 - 0) { /* spacing no-op */ }
    for (int i = tid; i < 512; i += 512)
        dsm[O_HS + i] = hidden_init[(b0 + (i >> 8)) * 256 + (i & 255)];
    __syncthreads();
    CLUSTER_SYNC();

#pragma unroll 1
    for (int t = 0; t < TT; t++) {
        // ---- (0) xproj prefetch by threads 128..175 (also do phase A after) ----
        if (tid >= 128 && tid < 176) {
            int idx = tid - 128;                   // 0..47
            int bb = idx / 24, rem = idx % 24;
            int g = rem >> 3, c8 = rem & 7;
            const float* src = g_xproj + (size_t)(t * 32 + b0 + bb) * 768
                             + g * 256 + q * 32 + c8 * 4;
            cp_async16(sbase + (O_XPS + bb * 96 + g * 32 + c8 * 4) * 4, src);
            CP_COMMIT();
        }

        // ---- (1) phase A: hcat, k split 4 ways over 512 threads ----
        {
            const int j = tid & 127;
            const int kq = tid >> 7;               // 0..3
            const float* wp = &dsm[O_WS + kq * 64 * 128 + j];
            const float* h0 = &dsm[O_HS + kq * 64];
            const float* h1 = &dsm[O_HS + 256 + kq * 64];
            float a0 = 0.f, a1 = 0.f;
#pragma unroll
            for (int k = 0; k < 64; k += 4) {
                float4 hv0 = *(const float4*)(h0 + k);
                float4 hv1 = *(const float4*)(h1 + k);
                float w0 = wp[k * 128], w1 = wp[(k + 1) * 128];
                float w2v = wp[(k + 2) * 128], w3 = wp[(k + 3) * 128];
                a0 += hv0.x * w0 + hv0.y * w1 + hv0.z * w2v + hv0.w * w3;
                a1 += hv1.x * w0 + hv1.y * w1 + hv1.z * w2v + hv1.w * w3;
            }
            dsm[O_PA + kq * 256 + j]       = a0;
            dsm[O_PA + kq * 256 + 128 + j] = a1;
        }
        __syncthreads();
        if (tid < 256) {
            int bb = tid >> 7, jj = tid & 127;
            float v = dsm[O_BS + jj]
                    + dsm[O_PA + bb * 128 + jj]       + dsm[O_PA + 256 + bb * 128 + jj]
                    + dsm[O_PA + 512 + bb * 128 + jj] + dsm[O_PA + 768 + bb * 128 + jj];
            dsm[O_HC + bb * 128 + jj] = v;
        }
        __syncthreads();

        // ---- (2) logits: 128 threads, transposed qproj tile (conflict-free) ----
        if (tid < 128) {
            const int bb = tid >> 6, s = tid & 63;
            const float* qt = &dsm[O_QT + bb * 2048 + s];
            const float* hq = &dsm[O_HC + bb * 128];
            const float* w2 = &dsm[O_W2];
            float u0 = 0.f, u1 = 0.f;
#pragma unroll
            for (int c = 0; c < 32; c += 4) {
                float4 hv = *(const float4*)(hq + c);
                float4 wv = *(const float4*)(w2 + c);
                u0 += wv.x * fmaxf(hv.x + qt[c * 64], 0.f)
                    + wv.y * fmaxf(hv.y + qt[(c + 1) * 64], 0.f);
                u1 += wv.z * fmaxf(hv.z + qt[(c + 2) * 64], 0.f)
                    + wv.w * fmaxf(hv.w + qt[(c + 3) * 64], 0.f);
            }
            float u = u0 + u1;
            uint32_t la = sbase + (O_UPA + (int)q * 128 + tid) * 4;
#pragma unroll
            for (int rk = 0; rk < 8; rk++)
                st_cluster_f32(mapa_u32(la, rk), u);
        }
        CLUSTER_SYNC();  // sync1: all logit partials delivered everywhere

        // ---- (3) softmax (redundant per rank) ----
        float u_v = 0.f, e_v = 0.f;
        if (tid < 128) {
#pragma unroll
            for (int r = 0; r < 8; r++) u_v += dsm[O_UPA + r * 128 + tid];
            float m = u_v;
#pragma unroll
            for (int o = 16; o; o >>= 1) m = fmaxf(m, __shfl_xor_sync(0xffffffffu, m, o));
            if ((tid & 31) == 0) red_m[tid >> 5] = m;
        }
        __syncthreads();
        if (tid < 128) {
            int bb = tid >> 6;
            float m = fmaxf(red_m[bb * 2], red_m[bb * 2 + 1]);
            e_v = __expf(u_v - m);
            float sum = e_v;
#pragma unroll
            for (int o = 16; o; o >>= 1) sum += __shfl_xor_sync(0xffffffffu, sum, o);
            if ((tid & 31) == 0) red_s[tid >> 5] = sum;
        }
        __syncthreads();
        if (tid < 128) {
            int bb = tid >> 6, s = tid & 63;
            float inv = 1.f / (red_s[bb * 2] + red_s[bb * 2 + 1]);
            float al = e_v * inv;
            dsm[O_AL + tid] = al;
            if (q == 0) att_out[((b0 + bb) * SS + s) * TT + t] = al;
        }
        CP_WAIT(0);
        __syncthreads();

        // ---- (4) gate sums: s split 2 ways over 384 threads ----
        if (tid < 384) {
            int half = tid >= 192;
            int idx = tid - half * 192;            // 0..191
            int bb = idx >= 96;
            int cc = idx - bb * 96;                // 0..95
            const float* tp = &dsm[O_TILE + bb * 6144 + half * 32 * 96 + cc];
            const float* ap = &dsm[O_AL + bb * 64 + half * 32];
            float acc0 = 0.f, acc1 = 0.f;
#pragma unroll 8
            for (int s = 0; s < 32; s += 2) {
                acc0 += ap[s] * tp[s * 96];
                acc1 += ap[s + 1] * tp[(s + 1) * 96];
            }
            dsm[O_GP + half * 192 + idx] = acc0 + acc1;
        }
        __syncthreads();
        if (tid < 192) {
            int bb = tid >= 96;
            int cc = tid - bb * 96;                // 0..95
            float pre = dsm[O_GP + tid] + dsm[O_GP + 192 + tid]
                      + dsm[O_XPS + bb * 96 + cc];
            if (cc < 64) {
                float v = 1.f / (1.f + __expf(-(pre + dsm[O_HC + bb * 128 + 32 + cc])));
                dsm[O_ZR + bb * 64 + cc] = v;
            } else {
                dsm[O_PHB + bb * 32 + cc - 64] = pre;
            }
        }
        __syncthreads();

        // ---- (5) GRU combine (local dims) + h broadcast ----
        if (tid < 64) {
            int bb = tid >> 5, jj = tid & 31;
            int dg = (int)q * 32 + jj;
            float z = dsm[O_ZR + bb * 64 + jj];
            float r = dsm[O_ZR + bb * 64 + 32 + jj];
            float g = tanhf(dsm[O_PHB + bb * 32 + jj] + r * dsm[O_HC + bb * 128 + 96 + jj]);
            float hold = dsm[O_HS + bb * 256 + dg];
            float hn = (1.f - z) * g + z * hold;
            uint32_t la = sbase + (O_HS + bb * 256 + dg) * 4;
#pragma unroll
            for (int rk = 0; rk < 8; rk++)
                st_cluster_f32(mapa_u32(la, rk), hn);
            __half hi = __float2half(hn);
            __half lo = __float2half(hn - __half2float(hi));
            size_t rb = (size_t)((b0 + bb) * 64 + t) * 512;
            g_Ah[rb + dg]       = hi;
            g_Ah[rb + 256 + dg] = lo;
        }
        CLUSTER_SYNC();  // sync2: new h visible everywhere
    }
}

// ---------------------------------------------------------------------------
// K4: HMMA fp16 GEMM. Trailing mainloop barrier removed (top sync suffices:
// readers of stage (kt-1)%3 finished before it; writers issue after it).
// ---------------------------------------------------------------------------
#define GSTAGES 3

__global__ void __launch_bounds__(256, 2)
gemm_mma_kernel(const float* __restrict__ bout, float* __restrict__ out) {
    __shared__ __align__(128) __half sA[GSTAGES][128 * 32];
    __shared__ __align__(128) __half sB[GSTAGES][128 * 32];

    const int tid  = threadIdx.x;
    const int lane = tid & 31, wid = tid >> 5;
    const int wr = wid >> 2, wc = wid & 3;
    const int row0 = blockIdx.x * 128, col0 = blockIdx.y * 128;

    const __half* Ag = g_Ah + (size_t)row0 * 512;
    const __half* Bg = g_Bh + (size_t)col0 * 256;

    const uint32_t sAb = smem_u32(sA);
    const uint32_t sBb = smem_u32(sB);

    const int rA0 = tid >> 2,          cA0 = tid & 3;
    const int rA1 = (tid + 256) >> 2;
    const uint32_t dA0 = rA0 * 64 + ((cA0 ^ ((rA0 >> 1) & 3)) * 16);
    const uint32_t dA1 = rA1 * 64 + ((cA0 ^ ((rA1 >> 1) & 3)) * 16);

#define LOAD_STAGE(s, kt) do {                                                       \
        uint32_t ab = sAb + (s) * 8192, bb = sBb + (s) * 8192;                       \
        int bk = ((kt) & 7) * 32;                                                    \
        cp_async16(ab + dA0, Ag + (size_t)rA0 * 512 + (kt) * 32 + cA0 * 8);          \
        cp_async16(ab + dA1, Ag + (size_t)rA1 * 512 + (kt) * 32 + cA0 * 8);          \
        cp_async16(bb + dA0, Bg + (size_t)rA0 * 256 + bk + cA0 * 8);                 \
        cp_async16(bb + dA1, Bg + (size_t)rA1 * 256 + bk + cA0 * 8);                 \
    } while (0)

    LOAD_STAGE(0, 0); CP_COMMIT();
    LOAD_STAGE(1, 1); CP_COMMIT();

    float acc[4][4][4];
#pragma unroll
    for (int i = 0; i < 4; i++)
#pragma unroll
        for (int j = 0; j < 4; j++)
#pragma unroll
            for (int qq = 0; qq < 4; qq++) acc[i][j][qq] = 0.f;

    const int aRow = lane & 15;
    const int aSel = lane >> 4;
    const int bRow = (lane & 7) + ((lane >> 4) << 3);
    const int bSel = (lane >> 3) & 1;

#pragma unroll 1
    for (int kt = 0; kt < 16; kt++) {
        CP_WAIT(1);
        __syncthreads();
        if (kt + 2 < 16) LOAD_STAGE((kt + 2) % GSTAGES, kt + 2);
        CP_COMMIT();

        const int st = kt % GSTAGES;
        const uint32_t ab = sAb + st * 8192;
        const uint32_t bb = sBb + st * 8192;

#pragma unroll
        for (int kf = 0; kf < 2; kf++) {
            uint32_t aF[4][4];
#pragma unroll
            for (int mf = 0; mf < 4; mf++) {
                int row = wr * 64 + mf * 16 + aRow;
                int ch  = (kf * 2 + aSel) ^ ((row >> 1) & 3);
                ldsm_x4(ab + row * 64 + ch * 16, aF[mf][0], aF[mf][1], aF[mf][2], aF[mf][3]);
            }
            uint32_t bF[2][4];
#pragma unroll
            for (int nf2 = 0; nf2 < 2; nf2++) {
                int row = wc * 32 + nf2 * 16 + bRow;
                int ch  = (kf * 2 + bSel) ^ ((row >> 1) & 3);
                ldsm_x4(bb + row * 64 + ch * 16, bF[nf2][0], bF[nf2][1], bF[nf2][2], bF[nf2][3]);
            }
#pragma unroll
            for (int mf = 0; mf < 4; mf++)
#pragma unroll
                for (int nf = 0; nf < 4; nf++) {
                    uint32_t b0 = bF[nf >> 1][(nf & 1) * 2 + 0];
                    uint32_t b1 = bF[nf >> 1][(nf & 1) * 2 + 1];
                    mma16816(acc[mf][nf], aF[mf], b0, b1);
                }
        }
        // trailing __syncthreads removed (provably redundant)
    }

    const int rq = lane >> 2, cq = (lane & 3) * 2;
    const int rbase = row0 + wr * 64, cbase = col0 + wc * 32;
#pragma unroll
    for (int mf = 0; mf < 4; mf++) {
#pragma unroll
        for (int nf = 0; nf < 4; nf++) {
            int r  = rbase + mf * 16 + rq;
            int cc = cbase + nf * 8 + cq;
            float bz0 = bout[cc], bz1 = bout[cc + 1];
            float2 v0 = make_float2(acc[mf][nf][0] + bz0, acc[mf][nf][1] + bz1);
            float2 v1 = make_float2(acc[mf][nf][2] + bz0, acc[mf][nf][3] + bz1);
            *(float2*)&out[(size_t)r * VV + cc]       = v0;
            *(float2*)&out[(size_t)(r + 8) * VV + cc] = v1;
        }
    }
#undef LOAD_STAGE
}

// ---------------------------------------------------------------------------
extern "C" void kernel_launch(void* const* d_in, const int* in_sizes, int n_in,
                              void* d_out, int out_size) {
    const int*   inputs = (const int*)  d_in[0];
    const float* ann    = (const float*)d_in[1];
    const float* hinit  = (const float*)d_in[2];
    const float* emb    = (const float*)d_in[3];
    const float* W1     = (const float*)d_in[4];
    const float* b1     = (const float*)d_in[5];
    const float* W2     = (const float*)d_in[6];
    /* b2 (d_in[7]) cancels in softmax */
    const float* Wiz    = (const float*)d_in[8];
    const float* biz    = (const float*)d_in[9];
    const float* Wir    = (const float*)d_in[10];
    const float* bir    = (const float*)d_in[11];
    const float* Wih    = (const float*)d_in[12];
    const float* bih    = (const float*)d_in[13];
    const float* Whz    = (const float*)d_in[14];
    const float* bhz    = (const float*)d_in[15];
    const float* Whr    = (const float*)d_in[16];
    const float* bhr    = (const float*)d_in[17];
    const float* Whh    = (const float*)d_in[18];
    const float* bhh    = (const float*)d_in[19];
    const float* Wout   = (const float*)d_in[20];
    const float* bout   = (const float*)d_in[21];

    float* out = (float*)d_out;
    float* att = out + (size_t)BB * TT * VV;

    static int attr_set = 0;
    if (!attr_set) {
        cudaFuncSetAttribute(recurrence_kernel,
                             cudaFuncAttributeMaxDynamicSharedMemorySize, REC_DSMEM);
        attr_set = 1;
    }

    prep_kernel<<<256, 256>>>(W1, Wiz, Wir, Wih, Whz, bhz, Whr, bhr, Whh, bhh);
    combo_kernel<<<4896, 128>>>(ann, emb, inputs, Wout, b1, biz, bir, bih);
    recurrence_kernel<<<128, 512, REC_DSMEM>>>(hinit, W2, att);
    gemm_mma_kernel<<<dim3(16, 250), 256>>>(bout, out);
}

// round 10
// speedup vs baseline: 1.3625x; 1.0244x over previous
#include <cuda_runtime.h>
#include <cuda_fp16.h>
#include <cstdint>

// Problem constants
#define BB   32
#define TT   64
#define SS   64
#define HH   256
#define VV   32000

// ---------------------------------------------------------------------------
// PTX helpers
// ---------------------------------------------------------------------------
__device__ __forceinline__ uint32_t smem_u32(const void* p) {
    uint32_t a;
    asm("{ .reg .u64 t; cvta.to.shared.u64 t, %1; cvt.u32.u64 %0, t; }" : "=r"(a) : "l"(p));
    return a;
}
__device__ __forceinline__ void cp_async16(uint32_t dst, const void* src) {
    asm volatile("cp.async.cg.shared.global [%0], [%1], 16;" :: "r"(dst), "l"(src));
}
#define CP_COMMIT() asm volatile("cp.async.commit_group;" ::: "memory")
#define CP_WAIT(n)  asm volatile("cp.async.wait_group %0;" :: "n"(n) : "memory")

__device__ __forceinline__ void ldsm_x4(uint32_t addr, uint32_t& r0, uint32_t& r1,
                                        uint32_t& r2, uint32_t& r3) {
    asm volatile("ldmatrix.sync.aligned.m8n8.x4.shared.b16 {%0,%1,%2,%3}, [%4];"
                 : "=r"(r0), "=r"(r1), "=r"(r2), "=r"(r3) : "r"(addr));
}
__device__ __forceinline__ void mma16816(float* c, const uint32_t* a,
                                         uint32_t b0, uint32_t b1) {
    asm volatile("mma.sync.aligned.m16n8k16.row.col.f32.f16.f16.f32 "
                 "{%0,%1,%2,%3}, {%4,%5,%6,%7}, {%8,%9}, {%0,%1,%2,%3};"
                 : "+f"(c[0]), "+f"(c[1]), "+f"(c[2]), "+f"(c[3])
                 : "r"(a[0]), "r"(a[1]), "r"(a[2]), "r"(a[3]), "r"(b0), "r"(b1));
}
__device__ __forceinline__ uint32_t ctarank() {
    uint32_t r; asm("mov.u32 %0, %%cluster_ctarank;" : "=r"(r)); return r;
}
__device__ __forceinline__ uint32_t mapa_u32(uint32_t laddr, uint32_t rank) {
    uint32_t r;
    asm("mapa.shared::cluster.u32 %0, %1, %2;" : "=r"(r) : "r"(laddr), "r"(rank));
    return r;
}
__device__ __forceinline__ void st_cluster_f32(uint32_t addr, float v) {
    asm volatile("st.shared::cluster.f32 [%0], %1;" :: "r"(addr), "f"(v) : "memory");
}
#define CLUSTER_SYNC() do { \
    asm volatile("barrier.cluster.arrive.aligned;" ::: "memory"); \
    asm volatile("barrier.cluster.wait.aligned;" ::: "memory"); \
} while (0)
#define CLUSTER_ARRIVE() asm volatile("barrier.cluster.arrive.aligned;" ::: "memory")
#define CLUSTER_WAIT()   asm volatile("barrier.cluster.wait.aligned;" ::: "memory")

// ---------------------------------------------------------------------------
// Device scratch
// ---------------------------------------------------------------------------
__device__ __align__(16) float g_Wcat[256 * 1024];     // [k][qproj|Whz|Whr|Whh]
__device__ __align__(16) float g_bcat[1024];
__device__ __align__(16) float g_Wann[256 * 1024];
__device__ __align__(16) float g_Wx[256 * 768];
__device__ __align__(16) float g_annprojB[2048 * 256]; // [(b*S+s)][256]  (+b1)
__device__ __align__(16) float g_annWi[2048 * 768];    // [(b*S+s)][768]
__device__ __align__(16) float g_xproj[2048 * 768];    // [(t*B+b)][768]  (+bi*)
__device__ __align__(16) __half g_Ah[2048 * 512];      // [A_hi(256)|A_lo(256)]
__device__ __align__(16) __half g_Bh[32000L * 256];    // B_hi, K-major

// ---------------------------------------------------------------------------
// K0: build fused weight matrices
// ---------------------------------------------------------------------------
__global__ void prep_kernel(const float* __restrict__ W1,
                            const float* __restrict__ Wiz, const float* __restrict__ Wir,
                            const float* __restrict__ Wih,
                            const float* __restrict__ Whz, const float* __restrict__ bhz,
                            const float* __restrict__ Whr, const float* __restrict__ bhr,
                            const float* __restrict__ Whh, const float* __restrict__ bhh) {
    int idx = blockIdx.x * blockDim.x + threadIdx.x;
    int stride = gridDim.x * blockDim.x;
    for (int i = idx; i < 256 * 1024; i += stride) {
        int k = i >> 10, j = i & 1023;
        float wc, wa;
        if (j < 256)      { wc = W1[k * 256 + j];          wa = W1[(256 + k) * 256 + j]; }
        else if (j < 512) { wc = Whz[k * 256 + j - 256];   wa = Wiz[k * 256 + j - 256]; }
        else if (j < 768) { wc = Whr[k * 256 + j - 512];   wa = Wir[k * 256 + j - 512]; }
        else              { wc = Whh[k * 256 + j - 768];   wa = Wih[k * 256 + j - 768]; }
        g_Wcat[i] = wc; g_Wann[i] = wa;
    }
    for (int i = idx; i < 256 * 768; i += stride) {
        int k = i / 768, j = i % 768;
        float w;
        if (j < 256)      w = Wiz[(256 + k) * 256 + j];
        else if (j < 512) w = Wir[(256 + k) * 256 + j - 256];
        else              w = Wih[(256 + k) * 256 + j - 512];
        g_Wx[i] = w;
    }
    for (int i = idx; i < 1024; i += stride) {
        float bv = 0.f;
        if (i >= 256 && i < 512)      bv = bhz[i - 256];
        else if (i >= 512 && i < 768) bv = bhr[i - 512];
        else if (i >= 768)            bv = bhh[i - 768];
        g_bcat[i] = bv;
    }
}

// ---------------------------------------------------------------------------
// K1 combo: sgemm mode1 (512 CTAs) + sgemm mode2 (384) + Wout->fp16 (4000)
// ---------------------------------------------------------------------------
__global__ void __launch_bounds__(128)
combo_kernel(const float* __restrict__ ann, const float* __restrict__ emb,
             const int* __restrict__ inputs, const float* __restrict__ Wout,
             const float* __restrict__ b1, const float* __restrict__ biz,
             const float* __restrict__ bir, const float* __restrict__ bih) {
    __shared__ __align__(16) float sm[2][64 * 20 + 16 * 68];
    __shared__ __align__(16) float sw[32 * 68];
    __shared__ int tok[64];

    const int bid = blockIdx.x, tid = threadIdx.x;

    if (bid >= 896) {
        int b3 = bid - 896;
        int k0 = (b3 & 7) * 32, n0 = (b3 >> 3) * 64;
        for (int i = tid; i < 32 * 64; i += 128) {
            int k = i >> 6, n = i & 63;
            sw[k * 68 + n] = Wout[(size_t)(k0 + k) * VV + n0 + n];
        }
        __syncthreads();
        const int n = tid >> 1, kh = (tid & 1) * 16;
        __align__(16) __half vals[16];
#pragma unroll
        for (int j = 0; j < 16; j++) vals[j] = __float2half(sw[(kh + j) * 68 + n]);
        __half* dst = g_Bh + (size_t)(n0 + n) * 256 + k0 + kh;
        *(uint4*)dst       = ((const uint4*)vals)[0];
        *(uint4*)(dst + 8) = ((const uint4*)vals)[1];
        return;
    }

    const bool m1 = bid < 512;
    int row0, col0, N;
    const float* Bm;
    if (m1) { row0 = (bid >> 4) * 64; col0 = (bid & 15) * 64; N = 1024; Bm = g_Wann; }
    else    { int b2 = bid - 512; row0 = (b2 / 12) * 64; col0 = (b2 % 12) * 64; N = 768; Bm = g_Wx; }

    if (!m1 && tid < 64) {
        int r = row0 + tid;
        tok[tid] = inputs[(r & 31) * TT + (r >> 5)];
    }
    if (!m1) __syncthreads();

    const int rA = tid >> 2, kqA = (tid & 3) * 4;
    const int kB = tid >> 4, nB = (tid & 15) * 4;
    const float* ArowA = m1 ? (ann + (size_t)(row0 + rA) * 256)
                            : (emb + (size_t)tok[rA] * 256);
    const float* ArowB = m1 ? (ann + (size_t)(row0 + rA + 32) * 256)
                            : (emb + (size_t)tok[rA + 32] * 256);
    const float* Bcol = Bm + col0;

    {
        float4 a0 = *(const float4*)(ArowA + kqA);
        float4 a1 = *(const float4*)(ArowB + kqA);
        float4 b0 = *(const float4*)(Bcol + (size_t)kB * N + nB);
        float4 b1v = *(const float4*)(Bcol + (size_t)(kB + 8) * N + nB);
        *(float4*)&sm[0][rA * 20 + kqA]        = a0;
        *(float4*)&sm[0][(rA + 32) * 20 + kqA] = a1;
        *(float4*)&sm[0][1280 + kB * 68 + nB]        = b0;
        *(float4*)&sm[0][1280 + (kB + 8) * 68 + nB]  = b1v;
    }
    __syncthreads();

    float acc[4][8];
#pragma unroll
    for (int i = 0; i < 4; i++)
#pragma unroll
        for (int j = 0; j < 8; j++) acc[i][j] = 0.f;

    const int ty4 = (tid >> 3) * 4, tx8 = (tid & 7) * 8;
    int buf = 0;

#pragma unroll 1
    for (int kt = 0; kt < 16; kt++) {
        float4 nA0, nA1, nB0, nB1;
        if (kt < 15) {
            int k0 = (kt + 1) * 16;
            nA0 = *(const float4*)(ArowA + k0 + kqA);
            nA1 = *(const float4*)(ArowB + k0 + kqA);
            nB0 = *(const float4*)(Bcol + (size_t)(k0 + kB) * N + nB);
            nB1 = *(const float4*)(Bcol + (size_t)(k0 + kB + 8) * N + nB);
        }
        const float* As_ = &sm[buf][0];
        const float* Bs_ = &sm[buf][1280];
#pragma unroll
        for (int kk = 0; kk < 16; kk++) {
            float a[4], b[8];
#pragma unroll
            for (int i = 0; i < 4; i++) a[i] = As_[(ty4 + i) * 20 + kk];
            *(float4*)&b[0] = *(const float4*)&Bs_[kk * 68 + tx8];
            *(float4*)&b[4] = *(const float4*)&Bs_[kk * 68 + tx8 + 4];
#pragma unroll
            for (int i = 0; i < 4; i++)
#pragma unroll
                for (int j = 0; j < 8; j++) acc[i][j] += a[i] * b[j];
        }
        if (kt < 15) {
            buf ^= 1;
            __syncthreads();
            *(float4*)&sm[buf][rA * 20 + kqA]        = nA0;
            *(float4*)&sm[buf][(rA + 32) * 20 + kqA] = nA1;
            *(float4*)&sm[buf][1280 + kB * 68 + nB]        = nB0;
            *(float4*)&sm[buf][1280 + (kB + 8) * 68 + nB]  = nB1;
            __syncthreads();
        }
    }

#pragma unroll
    for (int i = 0; i < 4; i++) {
        int r = row0 + ty4 + i;
#pragma unroll
        for (int j = 0; j < 8; j++) {
            int cidx = col0 + tx8 + j;
            float v = acc[i][j];
            if (m1) {
                if (cidx < 256) g_annprojB[(size_t)r * 256 + cidx] = v + b1[cidx];
                else            g_annWi[(size_t)r * 768 + (cidx - 256)] = v;
            } else {
                float bv = (cidx < 256) ? biz[cidx]
                         : (cidx < 512) ? bir[cidx - 256] : bih[cidx - 512];
                g_xproj[(size_t)r * 768 + cidx] = v + bv;
            }
        }
    }
}

// ---------------------------------------------------------------------------
// K3: clustered recurrence v4 — minimal serialization points.
// Per step: 4 __syncthreads + 2 cluster barriers (one split arrive/wait).
// 16 clusters x 8 CTAs x 2 batches; rank q owns 32 cols of each gate block.
// ---------------------------------------------------------------------------
// dsm float offsets
#define O_WS   0        // [k 0..255][j 0..127]  weights, j contiguous
#define O_QT   32768    // [bb][c 0..31][s 0..63] annproj transposed
#define O_TILE 36864    // [bb][s 0..63][c 0..95] annWi (z|r|h) pitch 96
#define O_HS   49152    // 2 x 256 hidden state
#define O_HC   49664    // 2 x 128 hcat slice
#define O_PA   49920    // 4 kq x (2 bb x 128 j) phase-A partials
#define O_UPA  50944    // 8 x 128 logit partials (all-gathered)
#define O_AL   51968    // 2 x 64 alpha
#define O_ZR   52096    // 2 x 64 (z | r)
#define O_PHB  52224    // 2 x 32 hbar pre
#define O_BS   52288    // 128 bias
#define O_W2   52416    // 32
#define REC_NF 52448
#define REC_DSMEM (REC_NF * 4)

__global__ void __launch_bounds__(512, 1) __cluster_dims__(8, 1, 1)
recurrence_kernel(const float* __restrict__ hidden_init,
                  const float* __restrict__ W2,
                  float* __restrict__ att_out) {
    extern __shared__ __align__(16) float dsm[];

    const int tid = threadIdx.x;
    const uint32_t q = ctarank();
    const int b0 = (blockIdx.x >> 3) * 2;
    const uint32_t sbase = smem_u32(dsm);

    // ---- init ----
    for (int i = tid; i < 256 * 128; i += 512) {
        int k = i >> 7, j = i & 127;
        int gcol = (j >> 5) * 256 + (int)q * 32 + (j & 31);
        dsm[O_WS + k * 128 + j] = g_Wcat[k * 1024 + gcol];
    }
    for (int i = tid; i < 2 * 32 * 64; i += 512) {
        int bb = i >> 11, c = (i >> 6) & 31, s = i & 63;
        dsm[O_QT + i] = g_annprojB[(size_t)((b0 + bb) * 64 + s) * 256 + q * 32 + c];
    }
    for (int i = tid; i < 2 * 64 * 96; i += 512) {
        int bb = i / 6144, rem = i % 6144;
        int s = rem / 96, c = rem % 96;
        dsm[O_TILE + i] = g_annWi[(size_t)((b0 + bb) * 64 + s) * 768
                                  + (c >> 5) * 256 + q * 32 + (c & 31)];
    }
    if (tid < 128) {
        int gcol = (tid >> 5) * 256 + (int)q * 32 + (tid & 31);
        dsm[O_BS + tid] = g_bcat[gcol];
    }
    if (tid >= 128 && tid < 160) dsm[O_W2 + tid - 128] = W2[q * 32 + (tid - 128)];
    for (int i = tid; i < 512; i += 512)
        dsm[O_HS + i] = hidden_init[(b0 + (i >> 8)) * 256 + (i & 255)];
    __syncthreads();
    CLUSTER_SYNC();

    // register xproj prefetch state (gate threads tid<192)
    const int gbb = (tid >= 96 && tid < 192) ? 1 : 0;
    const int gcc = (tid < 192) ? (tid - gbb * 96) : 0;
    const size_t xoff = (size_t)((gcc >> 5) * 256 + (int)q * 32 + (gcc & 31));
    float xp = 0.f;
    if (tid < 192)
        xp = g_xproj[(size_t)(0 * 32 + b0 + gbb) * 768 + xoff];

#pragma unroll 1
    for (int t = 0; t < TT; t++) {
        // ---- (1) phase A: hcat, k split 4 ways over 512 threads ----
        {
            const int j = tid & 127;
            const int kq = tid >> 7;               // 0..3
            const float* wp = &dsm[O_WS + kq * 64 * 128 + j];
            const float* h0 = &dsm[O_HS + kq * 64];
            const float* h1 = &dsm[O_HS + 256 + kq * 64];
            float a0 = 0.f, a1 = 0.f;
#pragma unroll
            for (int k = 0; k < 64; k += 4) {
                float4 hv0 = *(const float4*)(h0 + k);
                float4 hv1 = *(const float4*)(h1 + k);
                float w0 = wp[k * 128], w1 = wp[(k + 1) * 128];
                float w2v = wp[(k + 2) * 128], w3 = wp[(k + 3) * 128];
                a0 += hv0.x * w0 + hv0.y * w1 + hv0.z * w2v + hv0.w * w3;
                a1 += hv1.x * w0 + hv1.y * w1 + hv1.z * w2v + hv1.w * w3;
            }
            dsm[O_PA + kq * 256 + j]       = a0;
            dsm[O_PA + kq * 256 + 128 + j] = a1;
        }
        __syncthreads();                                       // s0
        if (tid < 256) {
            int bb = tid >> 7, jj = tid & 127;
            float v = dsm[O_BS + jj]
                    + dsm[O_PA + bb * 128 + jj]       + dsm[O_PA + 256 + bb * 128 + jj]
                    + dsm[O_PA + 512 + bb * 128 + jj] + dsm[O_PA + 768 + bb * 128 + jj];
            dsm[O_HC + bb * 128 + jj] = v;
        }
        __syncthreads();                                       // s1

        // ---- (2) logits: 128 threads, push to all 8 ranks ----
        if (tid < 128) {
            const int bb = tid >> 6, s = tid & 63;
            const float* qt = &dsm[O_QT + bb * 2048 + s];
            const float* hq = &dsm[O_HC + bb * 128];
            const float* w2 = &dsm[O_W2];
            float u0 = 0.f, u1 = 0.f;
#pragma unroll
            for (int c = 0; c < 32; c += 4) {
                float4 hv = *(const float4*)(hq + c);
                float4 wv = *(const float4*)(w2 + c);
                u0 += wv.x * fmaxf(hv.x + qt[c * 64], 0.f)
                    + wv.y * fmaxf(hv.y + qt[(c + 1) * 64], 0.f);
                u1 += wv.z * fmaxf(hv.z + qt[(c + 2) * 64], 0.f)
                    + wv.w * fmaxf(hv.w + qt[(c + 3) * 64], 0.f);
            }
            float u = u0 + u1;
            uint32_t la = sbase + (O_UPA + (int)q * 128 + tid) * 4;
#pragma unroll
            for (int rk = 0; rk < 8; rk++)
                st_cluster_f32(mapa_u32(la, rk), u);
        }
        CLUSTER_SYNC();                                        // CS1

        // ---- (3) softmax: warp-redundant, zero syncthreads inside ----
        if (tid < 64) {
            const int bb = tid >> 5, lane = tid & 31;
            float u0 = 0.f, u1 = 0.f;
#pragma unroll
            for (int r = 0; r < 8; r++) {
                u0 += dsm[O_UPA + r * 128 + bb * 64 + lane];
                u1 += dsm[O_UPA + r * 128 + bb * 64 + 32 + lane];
            }
            float m = fmaxf(u0, u1);
#pragma unroll
            for (int o = 16; o; o >>= 1) m = fmaxf(m, __shfl_xor_sync(0xffffffffu, m, o));
            float e0 = __expf(u0 - m), e1 = __expf(u1 - m);
            float sum = e0 + e1;
#pragma unroll
            for (int o = 16; o; o >>= 1) sum += __shfl_xor_sync(0xffffffffu, sum, o);
            float inv = 1.f / sum;
            float a0 = e0 * inv, a1 = e1 * inv;
            dsm[O_AL + bb * 64 + lane]      = a0;
            dsm[O_AL + bb * 64 + 32 + lane] = a1;
            if (q == 0) {
                att_out[((b0 + bb) * SS + lane) * TT + t]      = a0;
                att_out[((b0 + bb) * SS + 32 + lane) * TT + t] = a1;
            }
        }
        __syncthreads();                                       // s2

        // ---- (4) gate sums + activations (single pass, xp from register) ----
        if (tid < 192) {
            const float* tp = &dsm[O_TILE + gbb * 6144 + gcc];
            const float* ap = &dsm[O_AL + gbb * 64];
            float acc0 = 0.f, acc1 = 0.f;
#pragma unroll 8
            for (int s = 0; s < 64; s += 2) {
                acc0 += ap[s] * tp[s * 96];
                acc1 += ap[s + 1] * tp[(s + 1) * 96];
            }
            float pre = acc0 + acc1 + xp;
            if (gcc < 64) {
                float v = 1.f / (1.f + __expf(-(pre + dsm[O_HC + gbb * 128 + 32 + gcc])));
                dsm[O_ZR + gbb * 64 + gcc] = v;
            } else {
                dsm[O_PHB + gbb * 32 + gcc - 64] = pre;
            }
        }
        __syncthreads();                                       // s3

        // ---- (5) GRU combine + h broadcast ----
        if (tid < 64) {
            int bb = tid >> 5, jj = tid & 31;
            int dg = (int)q * 32 + jj;
            float z = dsm[O_ZR + bb * 64 + jj];
            float r = dsm[O_ZR + bb * 64 + 32 + jj];
            float g = tanhf(dsm[O_PHB + bb * 32 + jj] + r * dsm[O_HC + bb * 128 + 96 + jj]);
            float hold = dsm[O_HS + bb * 256 + dg];
            float hn = (1.f - z) * g + z * hold;
            uint32_t la = sbase + (O_HS + bb * 256 + dg) * 4;
#pragma unroll
            for (int rk = 0; rk < 8; rk++)
                st_cluster_f32(mapa_u32(la, rk), hn);
            __half hi = __float2half(hn);
            __half lo = __float2half(hn - __half2float(hi));
            size_t rb = (size_t)((b0 + bb) * 64 + t) * 512;
            g_Ah[rb + dg]       = hi;
            g_Ah[rb + 256 + dg] = lo;
        }
        CLUSTER_ARRIVE();                                      // CS2 arrive
        if (tid < 192 && t + 1 < TT)                           // prefetch next xproj
            xp = g_xproj[(size_t)((t + 1) * 32 + b0 + gbb) * 768 + xoff];
        CLUSTER_WAIT();                                        // CS2 wait
    }
}

// ---------------------------------------------------------------------------
// K4: HMMA fp16 GEMM (unchanged: 207 us, tensor 53%)
// ---------------------------------------------------------------------------
#define GSTAGES 3

__global__ void __launch_bounds__(256, 2)
gemm_mma_kernel(const float* __restrict__ bout, float* __restrict__ out) {
    __shared__ __align__(128) __half sA[GSTAGES][128 * 32];
    __shared__ __align__(128) __half sB[GSTAGES][128 * 32];

    const int tid  = threadIdx.x;
    const int lane = tid & 31, wid = tid >> 5;
    const int wr = wid >> 2, wc = wid & 3;
    const int row0 = blockIdx.x * 128, col0 = blockIdx.y * 128;

    const __half* Ag = g_Ah + (size_t)row0 * 512;
    const __half* Bg = g_Bh + (size_t)col0 * 256;

    const uint32_t sAb = smem_u32(sA);
    const uint32_t sBb = smem_u32(sB);

    const int rA0 = tid >> 2,          cA0 = tid & 3;
    const int rA1 = (tid + 256) >> 2;
    const uint32_t dA0 = rA0 * 64 + ((cA0 ^ ((rA0 >> 1) & 3)) * 16);
    const uint32_t dA1 = rA1 * 64 + ((cA0 ^ ((rA1 >> 1) & 3)) * 16);

#define LOAD_STAGE(s, kt) do {                                                       \
        uint32_t ab = sAb + (s) * 8192, bb = sBb + (s) * 8192;                       \
        int bk = ((kt) & 7) * 32;                                                    \
        cp_async16(ab + dA0, Ag + (size_t)rA0 * 512 + (kt) * 32 + cA0 * 8);          \
        cp_async16(ab + dA1, Ag + (size_t)rA1 * 512 + (kt) * 32 + cA0 * 8);          \
        cp_async16(bb + dA0, Bg + (size_t)rA0 * 256 + bk + cA0 * 8);                 \
        cp_async16(bb + dA1, Bg + (size_t)rA1 * 256 + bk + cA0 * 8);                 \
    } while (0)

    LOAD_STAGE(0, 0); CP_COMMIT();
    LOAD_STAGE(1, 1); CP_COMMIT();

    float acc[4][4][4];
#pragma unroll
    for (int i = 0; i < 4; i++)
#pragma unroll
        for (int j = 0; j < 4; j++)
#pragma unroll
            for (int qq = 0; qq < 4; qq++) acc[i][j][qq] = 0.f;

    const int aRow = lane & 15;
    const int aSel = lane >> 4;
    const int bRow = (lane & 7) + ((lane >> 4) << 3);
    const int bSel = (lane >> 3) & 1;

#pragma unroll 1
    for (int kt = 0; kt < 16; kt++) {
        CP_WAIT(1);
        __syncthreads();
        if (kt + 2 < 16) LOAD_STAGE((kt + 2) % GSTAGES, kt + 2);
        CP_COMMIT();

        const int st = kt % GSTAGES;
        const uint32_t ab = sAb + st * 8192;
        const uint32_t bb = sBb + st * 8192;

#pragma unroll
        for (int kf = 0; kf < 2; kf++) {
            uint32_t aF[4][4];
#pragma unroll
            for (int mf = 0; mf < 4; mf++) {
                int row = wr * 64 + mf * 16 + aRow;
                int ch  = (kf * 2 + aSel) ^ ((row >> 1) & 3);
                ldsm_x4(ab + row * 64 + ch * 16, aF[mf][0], aF[mf][1], aF[mf][2], aF[mf][3]);
            }
            uint32_t bF[2][4];
#pragma unroll
            for (int nf2 = 0; nf2 < 2; nf2++) {
                int row = wc * 32 + nf2 * 16 + bRow;
                int ch  = (kf * 2 + bSel) ^ ((row >> 1) & 3);
                ldsm_x4(bb + row * 64 + ch * 16, bF[nf2][0], bF[nf2][1], bF[nf2][2], bF[nf2][3]);
            }
#pragma unroll
            for (int mf = 0; mf < 4; mf++)
#pragma unroll
                for (int nf = 0; nf < 4; nf++) {
                    uint32_t b0 = bF[nf >> 1][(nf & 1) * 2 + 0];
                    uint32_t b1 = bF[nf >> 1][(nf & 1) * 2 + 1];
                    mma16816(acc[mf][nf], aF[mf], b0, b1);
                }
        }
    }

    const int rq = lane >> 2, cq = (lane & 3) * 2;
    const int rbase = row0 + wr * 64, cbase = col0 + wc * 32;
#pragma unroll
    for (int mf = 0; mf < 4; mf++) {
#pragma unroll
        for (int nf = 0; nf < 4; nf++) {
            int r  = rbase + mf * 16 + rq;
            int cc = cbase + nf * 8 + cq;
            float bz0 = bout[cc], bz1 = bout[cc + 1];
            float2 v0 = make_float2(acc[mf][nf][0] + bz0, acc[mf][nf][1] + bz1);
            float2 v1 = make_float2(acc[mf][nf][2] + bz0, acc[mf][nf][3] + bz1);
            *(float2*)&out[(size_t)r * VV + cc]       = v0;
            *(float2*)&out[(size_t)(r + 8) * VV + cc] = v1;
        }
    }
#undef LOAD_STAGE
}

// ---------------------------------------------------------------------------
extern "C" void kernel_launch(void* const* d_in, const int* in_sizes, int n_in,
                              void* d_out, int out_size) {
    const int*   inputs = (const int*)  d_in[0];
    const float* ann    = (const float*)d_in[1];
    const float* hinit  = (const float*)d_in[2];
    const float* emb    = (const float*)d_in[3];
    const float* W1     = (const float*)d_in[4];
    const float* b1     = (const float*)d_in[5];
    const float* W2     = (const float*)d_in[6];
    /* b2 (d_in[7]) cancels in softmax */
    const float* Wiz    = (const float*)d_in[8];
    const float* biz    = (const float*)d_in[9];
    const float* Wir    = (const float*)d_in[10];
    const float* bir    = (const float*)d_in[11];
    const float* Wih    = (const float*)d_in[12];
    const float* bih    = (const float*)d_in[13];
    const float* Whz    = (const float*)d_in[14];
    const float* bhz    = (const float*)d_in[15];
    const float* Whr    = (const float*)d_in[16];
    const float* bhr    = (const float*)d_in[17];
    const float* Whh    = (const float*)d_in[18];
    const float* bhh    = (const float*)d_in[19];
    const float* Wout   = (const float*)d_in[20];
    const float* bout   = (const float*)d_in[21];

    float* out = (float*)d_out;
    float* att = out + (size_t)BB * TT * VV;

    static int attr_set = 0;
    if (!attr_set) {
        cudaFuncSetAttribute(recurrence_kernel,
                             cudaFuncAttributeMaxDynamicSharedMemorySize, REC_DSMEM);
        attr_set = 1;
    }

    prep_kernel<<<256, 256>>>(W1, Wiz, Wir, Wih, Whz, bhz, Whr, bhr, Whh, bhh);
    combo_kernel<<<4896, 128>>>(ann, emb, inputs, Wout, b1, biz, bir, bih);
    recurrence_kernel<<<128, 512, REC_DSMEM>>>(hinit, W2, att);
    gemm_mma_kernel<<<dim3(16, 250), 256>>>(bout, out);
}

// round 12
// speedup vs baseline: 1.3874x; 1.0182x over previous
#include <cuda_runtime.h>
#include <cuda_fp16.h>
#include <cstdint>

// Problem constants
#define BB   32
#define TT   64
#define SS   64
#define HH   256
#define VV   32000

// ---------------------------------------------------------------------------
// PTX helpers
// ---------------------------------------------------------------------------
__device__ __forceinline__ uint32_t smem_u32(const void* p) {
    uint32_t a;
    asm("{ .reg .u64 t; cvta.to.shared.u64 t, %1; cvt.u32.u64 %0, t; }" : "=r"(a) : "l"(p));
    return a;
}
__device__ __forceinline__ void cp_async16(uint32_t dst, const void* src) {
    asm volatile("cp.async.cg.shared.global [%0], [%1], 16;" :: "r"(dst), "l"(src));
}
#define CP_COMMIT() asm volatile("cp.async.commit_group;" ::: "memory")
#define CP_WAIT(n)  asm volatile("cp.async.wait_group %0;" :: "n"(n) : "memory")

__device__ __forceinline__ void ldsm_x4(uint32_t addr, uint32_t& r0, uint32_t& r1,
                                        uint32_t& r2, uint32_t& r3) {
    asm volatile("ldmatrix.sync.aligned.m8n8.x4.shared.b16 {%0,%1,%2,%3}, [%4];"
                 : "=r"(r0), "=r"(r1), "=r"(r2), "=r"(r3) : "r"(addr));
}
__device__ __forceinline__ void mma16816(float* c, const uint32_t* a,
                                         uint32_t b0, uint32_t b1) {
    asm volatile("mma.sync.aligned.m16n8k16.row.col.f32.f16.f16.f32 "
                 "{%0,%1,%2,%3}, {%4,%5,%6,%7}, {%8,%9}, {%0,%1,%2,%3};"
                 : "+f"(c[0]), "+f"(c[1]), "+f"(c[2]), "+f"(c[3])
                 : "r"(a[0]), "r"(a[1]), "r"(a[2]), "r"(a[3]), "r"(b0), "r"(b1));
}
__device__ __forceinline__ uint32_t ctarank() {
    uint32_t r; asm("mov.u32 %0, %%cluster_ctarank;" : "=r"(r)); return r;
}
__device__ __forceinline__ uint32_t mapa_u32(uint32_t laddr, uint32_t rank) {
    uint32_t r;
    asm("mapa.shared::cluster.u32 %0, %1, %2;" : "=r"(r) : "r"(laddr), "r"(rank));
    return r;
}
__device__ __forceinline__ void st_cluster_f32(uint32_t addr, float v) {
    asm volatile("st.shared::cluster.f32 [%0], %1;" :: "r"(addr), "f"(v) : "memory");
}
#define CLUSTER_SYNC() do { \
    asm volatile("barrier.cluster.arrive.aligned;" ::: "memory"); \
    asm volatile("barrier.cluster.wait.aligned;" ::: "memory"); \
} while (0)
#define CLUSTER_ARRIVE() asm volatile("barrier.cluster.arrive.aligned;" ::: "memory")
#define CLUSTER_WAIT()   asm volatile("barrier.cluster.wait.aligned;" ::: "memory")

// ---------------------------------------------------------------------------
// Device scratch
// ---------------------------------------------------------------------------
__device__ __align__(16) float g_Wcat[256 * 1024];     // [k][qproj|Whz|Whr|Whh]
__device__ __align__(16) float g_bcat[1024];
__device__ __align__(16) float g_Wann[256 * 1024];
__device__ __align__(16) float g_Wx[256 * 768];
__device__ __align__(16) float g_annprojB[2048 * 256]; // [(b*S+s)][256]  (+b1)
__device__ __align__(16) float g_annWi[2048 * 768];    // [(b*S+s)][768]
__device__ __align__(16) float g_xproj[2048 * 768];    // [(t*B+b)][768]  (+bi*)
__device__ __align__(16) __half g_Ah[2048 * 512];      // [A_hi(256)|A_lo(256)]
__device__ __align__(16) __half g_Bh[32000L * 256];    // B_hi only, K-major

// ---------------------------------------------------------------------------
// K0: build fused weight matrices
// ---------------------------------------------------------------------------
__global__ void prep_kernel(const float* __restrict__ W1,
                            const float* __restrict__ Wiz, const float* __restrict__ Wir,
                            const float* __restrict__ Wih,
                            const float* __restrict__ Whz, const float* __restrict__ bhz,
                            const float* __restrict__ Whr, const float* __restrict__ bhr,
                            const float* __restrict__ Whh, const float* __restrict__ bhh) {
    int idx = blockIdx.x * blockDim.x + threadIdx.x;
    int stride = gridDim.x * blockDim.x;
    for (int i = idx; i < 256 * 1024; i += stride) {
        int k = i >> 10, j = i & 1023;
        float wc, wa;
        if (j < 256)      { wc = W1[k * 256 + j];          wa = W1[(256 + k) * 256 + j]; }
        else if (j < 512) { wc = Whz[k * 256 + j - 256];   wa = Wiz[k * 256 + j - 256]; }
        else if (j < 768) { wc = Whr[k * 256 + j - 512];   wa = Wir[k * 256 + j - 512]; }
        else              { wc = Whh[k * 256 + j - 768];   wa = Wih[k * 256 + j - 768]; }
        g_Wcat[i] = wc; g_Wann[i] = wa;
    }
    for (int i = idx; i < 256 * 768; i += stride) {
        int k = i / 768, j = i % 768;
        float w;
        if (j < 256)      w = Wiz[(256 + k) * 256 + j];
        else if (j < 512) w = Wir[(256 + k) * 256 + j - 256];
        else              w = Wih[(256 + k) * 256 + j - 512];
        g_Wx[i] = w;
    }
    for (int i = idx; i < 1024; i += stride) {
        float bv = 0.f;
        if (i >= 256 && i < 512)      bv = bhz[i - 256];
        else if (i >= 512 && i < 768) bv = bhr[i - 512];
        else if (i >= 768)            bv = bhh[i - 768];
        g_bcat[i] = bv;
    }
}

// ---------------------------------------------------------------------------
// K1 combo: sgemm mode1 (512 CTAs) + sgemm mode2 (384) + Wout->fp16 (4000)
// ---------------------------------------------------------------------------
__global__ void __launch_bounds__(128)
combo_kernel(const float* __restrict__ ann, const float* __restrict__ emb,
             const int* __restrict__ inputs, const float* __restrict__ Wout,
             const float* __restrict__ b1, const float* __restrict__ biz,
             const float* __restrict__ bir, const float* __restrict__ bih) {
    __shared__ __align__(16) float sm[2][64 * 20 + 16 * 68];
    __shared__ __align__(16) float sw[32 * 68];
    __shared__ int tok[64];

    const int bid = blockIdx.x, tid = threadIdx.x;

    if (bid >= 896) {
        int b3 = bid - 896;
        int k0 = (b3 & 7) * 32, n0 = (b3 >> 3) * 64;
        for (int i = tid; i < 32 * 64; i += 128) {
            int k = i >> 6, n = i & 63;
            sw[k * 68 + n] = Wout[(size_t)(k0 + k) * VV + n0 + n];
        }
        __syncthreads();
        const int n = tid >> 1, kh = (tid & 1) * 16;
        __align__(16) __half vals[16];
#pragma unroll
        for (int j = 0; j < 16; j++) vals[j] = __float2half(sw[(kh + j) * 68 + n]);
        __half* dst = g_Bh + (size_t)(n0 + n) * 256 + k0 + kh;
        *(uint4*)dst       = ((const uint4*)vals)[0];
        *(uint4*)(dst + 8) = ((const uint4*)vals)[1];
        return;
    }

    const bool m1 = bid < 512;
    int row0, col0, N;
    const float* Bm;
    if (m1) { row0 = (bid >> 4) * 64; col0 = (bid & 15) * 64; N = 1024; Bm = g_Wann; }
    else    { int b2 = bid - 512; row0 = (b2 / 12) * 64; col0 = (b2 % 12) * 64; N = 768; Bm = g_Wx; }

    if (!m1 && tid < 64) {
        int r = row0 + tid;
        tok[tid] = inputs[(r & 31) * TT + (r >> 5)];
    }
    if (!m1) __syncthreads();

    const int rA = tid >> 2, kqA = (tid & 3) * 4;
    const int kB = tid >> 4, nB = (tid & 15) * 4;
    const float* ArowA = m1 ? (ann + (size_t)(row0 + rA) * 256)
                            : (emb + (size_t)tok[rA] * 256);
    const float* ArowB = m1 ? (ann + (size_t)(row0 + rA + 32) * 256)
                            : (emb + (size_t)tok[rA + 32] * 256);
    const float* Bcol = Bm + col0;

    {
        float4 a0 = *(const float4*)(ArowA + kqA);
        float4 a1 = *(const float4*)(ArowB + kqA);
        float4 b0 = *(const float4*)(Bcol + (size_t)kB * N + nB);
        float4 b1v = *(const float4*)(Bcol + (size_t)(kB + 8) * N + nB);
        *(float4*)&sm[0][rA * 20 + kqA]        = a0;
        *(float4*)&sm[0][(rA + 32) * 20 + kqA] = a1;
        *(float4*)&sm[0][1280 + kB * 68 + nB]        = b0;
        *(float4*)&sm[0][1280 + (kB + 8) * 68 + nB]  = b1v;
    }
    __syncthreads();

    float acc[4][8];
#pragma unroll
    for (int i = 0; i < 4; i++)
#pragma unroll
        for (int j = 0; j < 8; j++) acc[i][j] = 0.f;

    const int ty4 = (tid >> 3) * 4, tx8 = (tid & 7) * 8;
    int buf = 0;

#pragma unroll 1
    for (int kt = 0; kt < 16; kt++) {
        float4 nA0, nA1, nB0, nB1;
        if (kt < 15) {
            int k0 = (kt + 1) * 16;
            nA0 = *(const float4*)(ArowA + k0 + kqA);
            nA1 = *(const float4*)(ArowB + k0 + kqA);
            nB0 = *(const float4*)(Bcol + (size_t)(k0 + kB) * N + nB);
            nB1 = *(const float4*)(Bcol + (size_t)(k0 + kB + 8) * N + nB);
        }
        const float* As_ = &sm[buf][0];
        const float* Bs_ = &sm[buf][1280];
#pragma unroll
        for (int kk = 0; kk < 16; kk++) {
            float a[4], b[8];
#pragma unroll
            for (int i = 0; i < 4; i++) a[i] = As_[(ty4 + i) * 20 + kk];
            *(float4*)&b[0] = *(const float4*)&Bs_[kk * 68 + tx8];
            *(float4*)&b[4] = *(const float4*)&Bs_[kk * 68 + tx8 + 4];
#pragma unroll
            for (int i = 0; i < 4; i++)
#pragma unroll
                for (int j = 0; j < 8; j++) acc[i][j] += a[i] * b[j];
        }
        if (kt < 15) {
            buf ^= 1;
            __syncthreads();
            *(float4*)&sm[buf][rA * 20 + kqA]        = nA0;
            *(float4*)&sm[buf][(rA + 32) * 20 + kqA] = nA1;
            *(float4*)&sm[buf][1280 + kB * 68 + nB]        = nB0;
            *(float4*)&sm[buf][1280 + (kB + 8) * 68 + nB]  = nB1;
            __syncthreads();
        }
    }

#pragma unroll
    for (int i = 0; i < 4; i++) {
        int r = row0 + ty4 + i;
#pragma unroll
        for (int j = 0; j < 8; j++) {
            int cidx = col0 + tx8 + j;
            float v = acc[i][j];
            if (m1) {
                if (cidx < 256) g_annprojB[(size_t)r * 256 + cidx] = v + b1[cidx];
                else            g_annWi[(size_t)r * 768 + (cidx - 256)] = v;
            } else {
                float bv = (cidx < 256) ? biz[cidx]
                         : (cidx < 512) ? bir[cidx - 256] : bih[cidx - 512];
                g_xproj[(size_t)r * 768 + cidx] = v + bv;
            }
        }
    }
}

// ---------------------------------------------------------------------------
// K3: clustered recurrence (identical to R10 - passing at ~440us)
// ---------------------------------------------------------------------------
#define O_WS   0        // [k 0..255][j 0..127]  weights, j contiguous
#define O_QT   32768    // [bb][c 0..31][s 0..63] annproj transposed
#define O_TILE 36864    // [bb][s 0..63][c 0..95] annWi (z|r|h) pitch 96
#define O_HS   49152    // 2 x 256 hidden state
#define O_HC   49664    // 2 x 128 hcat slice
#define O_PA   49920    // 4 kq x (2 bb x 128 j) phase-A partials
#define O_UPA  50944    // 8 x 128 logit partials (all-gathered)
#define O_AL   51968    // 2 x 64 alpha
#define O_ZR   52096    // 2 x 64 (z | r)
#define O_PHB  52224    // 2 x 32 hbar pre
#define O_BS   52288    // 128 bias
#define O_W2   52416    // 32
#define REC_NF 52448
#define REC_DSMEM (REC_NF * 4)

__global__ void __launch_bounds__(512, 1) __cluster_dims__(8, 1, 1)
recurrence_kernel(const float* __restrict__ hidden_init,
                  const float* __restrict__ W2,
                  float* __restrict__ att_out) {
    extern __shared__ __align__(16) float dsm[];

    const int tid = threadIdx.x;
    const uint32_t q = ctarank();
    const int b0 = (blockIdx.x >> 3) * 2;
    const uint32_t sbase = smem_u32(dsm);

    // ---- init ----
    for (int i = tid; i < 256 * 128; i += 512) {
        int k = i >> 7, j = i & 127;
        int gcol = (j >> 5) * 256 + (int)q * 32 + (j & 31);
        dsm[O_WS + k * 128 + j] = g_Wcat[k * 1024 + gcol];
    }
    for (int i = tid; i < 2 * 32 * 64; i += 512) {
        int bb = i >> 11, c = (i >> 6) & 31, s = i & 63;
        dsm[O_QT + i] = g_annprojB[(size_t)((b0 + bb) * 64 + s) * 256 + q * 32 + c];
    }
    for (int i = tid; i < 2 * 64 * 96; i += 512) {
        int bb = i / 6144, rem = i % 6144;
        int s = rem / 96, c = rem % 96;
        dsm[O_TILE + i] = g_annWi[(size_t)((b0 + bb) * 64 + s) * 768
                                  + (c >> 5) * 256 + q * 32 + (c & 31)];
    }
    if (tid < 128) {
        int gcol = (tid >> 5) * 256 + (int)q * 32 + (tid & 31);
        dsm[O_BS + tid] = g_bcat[gcol];
    }
    if (tid >= 128 && tid < 160) dsm[O_W2 + tid - 128] = W2[q * 32 + (tid - 128)];
    for (int i = tid; i < 512; i += 512)
        dsm[O_HS + i] = hidden_init[(b0 + (i >> 8)) * 256 + (i & 255)];
    __syncthreads();
    CLUSTER_SYNC();

    // register xproj prefetch state (gate threads tid<192)
    const int gbb = (tid >= 96 && tid < 192) ? 1 : 0;
    const int gcc = (tid < 192) ? (tid - gbb * 96) : 0;
    const size_t xoff = (size_t)((gcc >> 5) * 256 + (int)q * 32 + (gcc & 31));
    float xp = 0.f;
    if (tid < 192)
        xp = g_xproj[(size_t)(b0 + gbb) * 768 + xoff];

#pragma unroll 1
    for (int t = 0; t < TT; t++) {
        // ---- (1) phase A: hcat, k split 4 ways over 512 threads ----
        {
            const int j = tid & 127;
            const int kq = tid >> 7;               // 0..3
            const float* wp = &dsm[O_WS + kq * 64 * 128 + j];
            const float* h0 = &dsm[O_HS + kq * 64];
            const float* h1 = &dsm[O_HS + 256 + kq * 64];
            float a0 = 0.f, a1 = 0.f;
#pragma unroll
            for (int k = 0; k < 64; k += 4) {
                float4 hv0 = *(const float4*)(h0 + k);
                float4 hv1 = *(const float4*)(h1 + k);
                float w0 = wp[k * 128], w1 = wp[(k + 1) * 128];
                float w2v = wp[(k + 2) * 128], w3 = wp[(k + 3) * 128];
                a0 += hv0.x * w0 + hv0.y * w1 + hv0.z * w2v + hv0.w * w3;
                a1 += hv1.x * w0 + hv1.y * w1 + hv1.z * w2v + hv1.w * w3;
            }
            dsm[O_PA + kq * 256 + j]       = a0;
            dsm[O_PA + kq * 256 + 128 + j] = a1;
        }
        __syncthreads();                                       // s0
        if (tid < 256) {
            int bb = tid >> 7, jj = tid & 127;
            float v = dsm[O_BS + jj]
                    + dsm[O_PA + bb * 128 + jj]       + dsm[O_PA + 256 + bb * 128 + jj]
                    + dsm[O_PA + 512 + bb * 128 + jj] + dsm[O_PA + 768 + bb * 128 + jj];
            dsm[O_HC + bb * 128 + jj] = v;
        }
        __syncthreads();                                       // s1

        // ---- (2) logits: 128 threads, push to all 8 ranks ----
        if (tid < 128) {
            const int bb = tid >> 6, s = tid & 63;
            const float* qt = &dsm[O_QT + bb * 2048 + s];
            const float* hq = &dsm[O_HC + bb * 128];
            const float* w2 = &dsm[O_W2];
            float u0 = 0.f, u1 = 0.f;
#pragma unroll
            for (int c = 0; c < 32; c += 4) {
                float4 hv = *(const float4*)(hq + c);
                float4 wv = *(const float4*)(w2 + c);
                u0 += wv.x * fmaxf(hv.x + qt[c * 64], 0.f)
                    + wv.y * fmaxf(hv.y + qt[(c + 1) * 64], 0.f);
                u1 += wv.z * fmaxf(hv.z + qt[(c + 2) * 64], 0.f)
                    + wv.w * fmaxf(hv.w + qt[(c + 3) * 64], 0.f);
            }
            float u = u0 + u1;
            uint32_t la = sbase + (O_UPA + (int)q * 128 + tid) * 4;
#pragma unroll
            for (int rk = 0; rk < 8; rk++)
                st_cluster_f32(mapa_u32(la, rk), u);
        }
        CLUSTER_SYNC();                                        // CS1

        // ---- (3) softmax: warp-redundant, zero syncthreads inside ----
        if (tid < 64) {
            const int bb = tid >> 5, lane = tid & 31;
            float u0 = 0.f, u1 = 0.f;
#pragma unroll
            for (int r = 0; r < 8; r++) {
                u0 += dsm[O_UPA + r * 128 + bb * 64 + lane];
                u1 += dsm[O_UPA + r * 128 + bb * 64 + 32 + lane];
            }
            float m = fmaxf(u0, u1);
#pragma unroll
            for (int o = 16; o; o >>= 1) m = fmaxf(m, __shfl_xor_sync(0xffffffffu, m, o));
            float e0 = __expf(u0 - m), e1 = __expf(u1 - m);
            float sum = e0 + e1;
#pragma unroll
            for (int o = 16; o; o >>= 1) sum += __shfl_xor_sync(0xffffffffu, sum, o);
            float inv = 1.f / sum;
            float a0 = e0 * inv, a1 = e1 * inv;
            dsm[O_AL + bb * 64 + lane]      = a0;
            dsm[O_AL + bb * 64 + 32 + lane] = a1;
            if (q == 0) {
                att_out[((b0 + bb) * SS + lane) * TT + t]      = a0;
                att_out[((b0 + bb) * SS + 32 + lane) * TT + t] = a1;
            }
        }
        __syncthreads();                                       // s2

        // ---- (4) gate sums + activations (single pass, xp from register) ----
        if (tid < 192) {
            const float* tp = &dsm[O_TILE + gbb * 6144 + gcc];
            const float* ap = &dsm[O_AL + gbb * 64];
            float acc0 = 0.f, acc1 = 0.f;
#pragma unroll 8
            for (int s = 0; s < 64; s += 2) {
                acc0 += ap[s] * tp[s * 96];
                acc1 += ap[s + 1] * tp[(s + 1) * 96];
            }
            float pre = acc0 + acc1 + xp;
            if (gcc < 64) {
                float v = 1.f / (1.f + __expf(-(pre + dsm[O_HC + gbb * 128 + 32 + gcc])));
                dsm[O_ZR + gbb * 64 + gcc] = v;
            } else {
                dsm[O_PHB + gbb * 32 + gcc - 64] = pre;
            }
        }
        __syncthreads();                                       // s3

        // ---- (5) GRU combine + h broadcast ----
        if (tid < 64) {
            int bb = tid >> 5, jj = tid & 31;
            int dg = (int)q * 32 + jj;
            float z = dsm[O_ZR + bb * 64 + jj];
            float r = dsm[O_ZR + bb * 64 + 32 + jj];
            float g = tanhf(dsm[O_PHB + bb * 32 + jj] + r * dsm[O_HC + bb * 128 + 96 + jj]);
            float hold = dsm[O_HS + bb * 256 + dg];
            float hn = (1.f - z) * g + z * hold;
            uint32_t la = sbase + (O_HS + bb * 256 + dg) * 4;
#pragma unroll
            for (int rk = 0; rk < 8; rk++)
                st_cluster_f32(mapa_u32(la, rk), hn);
            __half hi = __float2half(hn);
            __half lo = __float2half(hn - __half2float(hi));
            size_t rb = (size_t)((b0 + bb) * 64 + t) * 512;
            g_Ah[rb + dg]       = hi;
            g_Ah[rb + 256 + dg] = lo;
        }
        CLUSTER_ARRIVE();                                      // CS2 arrive
        if (tid < 192 && t + 1 < TT)                           // prefetch next xproj
            xp = g_xproj[(size_t)((t + 1) * 32 + b0 + gbb) * 768 + xoff];
        CLUSTER_WAIT();                                        // CS2 wait
    }
}

// ---------------------------------------------------------------------------
// K4: HMMA fp16 GEMM — 64x64 warp tiles (4 warps, 128 threads, CTA 128x128).
// Halves LDSM bytes per MAC vs 64x32 tiles: smem crossbar no longer
// co-saturated with the tensor pipe.
// ---------------------------------------------------------------------------
#define GSTAGES 3

__global__ void __launch_bounds__(128, 2)
gemm_mma_kernel(const float* __restrict__ bout, float* __restrict__ out) {
    __shared__ __align__(128) __half sA[GSTAGES][128 * 32];
    __shared__ __align__(128) __half sB[GSTAGES][128 * 32];

    const int tid  = threadIdx.x;
    const int lane = tid & 31, wid = tid >> 5;
    const int wr = wid >> 1, wc = wid & 1;           // 2 x 2 grid of 64x64
    const int row0 = blockIdx.x * 128, col0 = blockIdx.y * 128;

    const __half* Ag = g_Ah + (size_t)row0 * 512;
    const __half* Bg = g_Bh + (size_t)col0 * 256;

    const uint32_t sAb = smem_u32(sA);
    const uint32_t sBb = smem_u32(sB);

    // loader: thread covers chunks tid, tid+128, tid+256, tid+384 (A and B)
    const int cA0 = tid & 3;
    const int rL  = tid >> 2;                         // base row 0..31

#define LOAD_STAGE(s, kt) do {                                                        \
        uint32_t ab = sAb + (s) * 8192, bbx = sBb + (s) * 8192;                       \
        int bk = ((kt) & 7) * 32;                                                     \
        _Pragma("unroll")                                                             \
        for (int ii = 0; ii < 4; ii++) {                                              \
            int r = rL + ii * 32;                                                     \
            uint32_t doff = r * 64 + ((cA0 ^ ((r >> 1) & 3)) * 16);                   \
            cp_async16(ab + doff,  Ag + (size_t)r * 512 + (kt) * 32 + cA0 * 8);       \
            cp_async16(bbx + doff, Bg + (size_t)r * 256 + bk + cA0 * 8);              \
        }                                                                             \
    } while (0)

    LOAD_STAGE(0, 0); CP_COMMIT();
    LOAD_STAGE(1, 1); CP_COMMIT();

    float acc[4][8][4];
#pragma unroll
    for (int i = 0; i < 4; i++)
#pragma unroll
        for (int j = 0; j < 8; j++)
#pragma unroll
            for (int qq = 0; qq < 4; qq++) acc[i][j][qq] = 0.f;

    const int aRow = lane & 15;
    const int aSel = lane >> 4;
    const int bRow = (lane & 7) + ((lane >> 4) << 3);
    const int bSel = (lane >> 3) & 1;

#pragma unroll 1
    for (int kt = 0; kt < 16; kt++) {
        CP_WAIT(1);
        __syncthreads();
        if (kt + 2 < 16) LOAD_STAGE((kt + 2) % GSTAGES, kt + 2);
        CP_COMMIT();

        const int st = kt % GSTAGES;
        const uint32_t ab = sAb + st * 8192;
        const uint32_t bb = sBb + st * 8192;

#pragma unroll
        for (int kf = 0; kf < 2; kf++) {
            uint32_t aF[4][4];
#pragma unroll
            for (int mf = 0; mf < 4; mf++) {
                int row = wr * 64 + mf * 16 + aRow;
                int ch  = (kf * 2 + aSel) ^ ((row >> 1) & 3);
                ldsm_x4(ab + row * 64 + ch * 16, aF[mf][0], aF[mf][1], aF[mf][2], aF[mf][3]);
            }
            uint32_t bF[4][4];
#pragma unroll
            for (int nf2 = 0; nf2 < 4; nf2++) {
                int row = wc * 64 + nf2 * 16 + bRow;
                int ch  = (kf * 2 + bSel) ^ ((row >> 1) & 3);
                ldsm_x4(bb + row * 64 + ch * 16, bF[nf2][0], bF[nf2][1], bF[nf2][2], bF[nf2][3]);
            }
#pragma unroll
            for (int mf = 0; mf < 4; mf++)
#pragma unroll
                for (int nf = 0; nf < 8; nf++) {
                    uint32_t b0 = bF[nf >> 1][(nf & 1) * 2 + 0];
                    uint32_t b1 = bF[nf >> 1][(nf & 1) * 2 + 1];
                    mma16816(acc[mf][nf], aF[mf], b0, b1);
                }
        }
    }

    const int rq = lane >> 2, cq = (lane & 3) * 2;
    const int rbase = row0 + wr * 64, cbase = col0 + wc * 64;
#pragma unroll
    for (int mf = 0; mf < 4; mf++) {
#pragma unroll
        for (int nf = 0; nf < 8; nf++) {
            int r  = rbase + mf * 16 + rq;
            int cc = cbase + nf * 8 + cq;
            float bz0 = bout[cc], bz1 = bout[cc + 1];
            float2 v0 = make_float2(acc[mf][nf][0] + bz0, acc[mf][nf][1] + bz1);
            float2 v1 = make_float2(acc[mf][nf][2] + bz0, acc[mf][nf][3] + bz1);
            *(float2*)&out[(size_t)r * VV + cc]       = v0;
            *(float2*)&out[(size_t)(r + 8) * VV + cc] = v1;
        }
    }
#undef LOAD_STAGE
}

// ---------------------------------------------------------------------------
extern "C" void kernel_launch(void* const* d_in, const int* in_sizes, int n_in,
                              void* d_out, int out_size) {
    const int*   inputs = (const int*)  d_in[0];
    const float* ann    = (const float*)d_in[1];
    const float* hinit  = (const float*)d_in[2];
    const float* emb    = (const float*)d_in[3];
    const float* W1     = (const float*)d_in[4];
    const float* b1     = (const float*)d_in[5];
    const float* W2     = (const float*)d_in[6];
    /* b2 (d_in[7]) cancels in softmax */
    const float* Wiz    = (const float*)d_in[8];
    const float* biz    = (const float*)d_in[9];
    const float* Wir    = (const float*)d_in[10];
    const float* bir    = (const float*)d_in[11];
    const float* Wih    = (const float*)d_in[12];
    const float* bih    = (const float*)d_in[13];
    const float* Whz    = (const float*)d_in[14];
    const float* bhz    = (const float*)d_in[15];
    const float* Whr    = (const float*)d_in[16];
    const float* bhr    = (const float*)d_in[17];
    const float* Whh    = (const float*)d_in[18];
    const float* bhh    = (const float*)d_in[19];
    const float* Wout   = (const float*)d_in[20];
    const float* bout   = (const float*)d_in[21];

    float* out = (float*)d_out;
    float* att = out + (size_t)BB * TT * VV;

    static int attr_set = 0;
    if (!attr_set) {
        cudaFuncSetAttribute(recurrence_kernel,
                             cudaFuncAttributeMaxDynamicSharedMemorySize, REC_DSMEM);
        attr_set = 1;
    }

    prep_kernel<<<256, 256>>>(W1, Wiz, Wir, Wih, Whz, bhz, Whr, bhr, Whh, bhh);
    combo_kernel<<<4896, 128>>>(ann, emb, inputs, Wout, b1, biz, bir, bih);
    recurrence_kernel<<<128, 512, REC_DSMEM>>>(hinit, W2, att);
    gemm_mma_kernel<<<dim3(16, 250), 128>>>(bout, out);
}